// round 1
// baseline (speedup 1.0000x reference)
#include <cuda_runtime.h>
#include <math.h>

// Problem constants (match reference setup_inputs)
#define NN 50000
#define NE 300000

// ---------------- scratch (device globals; no runtime allocation) ----------
__device__ float    g_h   [(size_t)NN * 512];   // GAT transform h = x @ W  (max HW=512)
__device__ float    g_lin [(size_t)NN * 256];   // linear residual buffer
__device__ float    g_agg [(size_t)NN * 512];   // per-dst aggregation
__device__ float    g_buf0[(size_t)NN * 256];   // layer-0 output
__device__ float    g_buf1[(size_t)NN * 256];   // layer-1 output
__device__ float    g_asrc[NN * 4];
__device__ float    g_adst[NN * 4];
__device__ unsigned g_m   [NN * 4];             // encoded float max
__device__ float    g_den [NN * 4];
__device__ float    g_e   [NE * 4];             // per-edge scores / exp

// ---------------- helpers ---------------------------------------------------
__device__ __forceinline__ unsigned fenc(float f) {
    unsigned u = __float_as_uint(f);
    return (u & 0x80000000u) ? ~u : (u | 0x80000000u);
}
__device__ __forceinline__ float fdec(unsigned u) {
    return (u & 0x80000000u) ? __uint_as_float(u ^ 0x80000000u)
                             : __uint_as_float(~u);
}

// ---------------- SGEMM: C[M,N] = A[M,K] @ B[K,N] (+bias) -------------------
// BM=BN=128, BK=8, 256 threads, 8x8 per thread. K multiple of 8, N multiple of 128.
__global__ __launch_bounds__(256)
void sgemm_kernel(const float* __restrict__ A, const float* __restrict__ B,
                  const float* __restrict__ bias, float* __restrict__ C,
                  int M, int K, int N) {
    __shared__ float As[8][128];
    __shared__ float Bs[8][128];
    const int tid  = threadIdx.x;
    const int tx   = tid & 15;          // 0..15 (N dir)
    const int ty   = tid >> 4;          // 0..15 (M dir)
    const int rowA = tid >> 1;          // 0..127
    const int colA = (tid & 1) * 4;     // 0 or 4
    const int rowB = tid >> 5;          // 0..7
    const int colB = (tid & 31) * 4;    // 0..124
    const int mBase = blockIdx.y * 128;
    const int nBase = blockIdx.x * 128;

    float acc[8][8];
#pragma unroll
    for (int i = 0; i < 8; i++)
#pragma unroll
        for (int j = 0; j < 8; j++) acc[i][j] = 0.f;

    const int   mA  = mBase + rowA;
    const bool  aok = (mA < M);
    const float* Ap = A + (size_t)mA * K + colA;
    const float* Bp = B + (size_t)rowB * N + nBase + colB;

    for (int k0 = 0; k0 < K; k0 += 8) {
        float4 a4 = aok ? *reinterpret_cast<const float4*>(Ap + k0)
                        : make_float4(0.f, 0.f, 0.f, 0.f);
        float4 b4 = *reinterpret_cast<const float4*>(Bp + (size_t)k0 * N);
        As[colA + 0][rowA] = a4.x;
        As[colA + 1][rowA] = a4.y;
        As[colA + 2][rowA] = a4.z;
        As[colA + 3][rowA] = a4.w;
        *reinterpret_cast<float4*>(&Bs[rowB][colB]) = b4;
        __syncthreads();
#pragma unroll
        for (int k = 0; k < 8; k++) {
            float4 a0 = *reinterpret_cast<const float4*>(&As[k][ty * 8]);
            float4 a1 = *reinterpret_cast<const float4*>(&As[k][ty * 8 + 4]);
            float4 b0 = *reinterpret_cast<const float4*>(&Bs[k][tx * 8]);
            float4 b1 = *reinterpret_cast<const float4*>(&Bs[k][tx * 8 + 4]);
            float ar[8] = {a0.x, a0.y, a0.z, a0.w, a1.x, a1.y, a1.z, a1.w};
            float br[8] = {b0.x, b0.y, b0.z, b0.w, b1.x, b1.y, b1.z, b1.w};
#pragma unroll
            for (int i = 0; i < 8; i++)
#pragma unroll
                for (int j = 0; j < 8; j++) acc[i][j] += ar[i] * br[j];
        }
        __syncthreads();
    }

#pragma unroll
    for (int i = 0; i < 8; i++) {
        int row = mBase + ty * 8 + i;
        if (row < M) {
            float* Cp = C + (size_t)row * N + nBase + tx * 8;
#pragma unroll
            for (int j = 0; j < 8; j++) {
                float v = acc[i][j];
                if (bias) v += bias[nBase + tx * 8 + j];
                Cp[j] = v;
            }
        }
    }
}

// ---------------- per-node attention dot products ---------------------------
// one warp per node; a_src[n,h] = <h[n,h,:], att_s[h,:]>, same for dst.
__global__ void attn_kernel(const float* __restrict__ h,
                            const float* __restrict__ att_s,
                            const float* __restrict__ att_d,
                            float* __restrict__ asrc, float* __restrict__ adst,
                            int n, int C) {
    int warp = (blockIdx.x * blockDim.x + threadIdx.x) >> 5;
    int lane = threadIdx.x & 31;
    if (warp >= n) return;
    const float* hr = h + (size_t)warp * 4 * C;
#pragma unroll
    for (int hh = 0; hh < 4; hh++) {
        float s1 = 0.f, s2 = 0.f;
        for (int c = lane; c < C; c += 32) {
            float v = hr[hh * C + c];
            s1 += v * att_s[hh * C + c];
            s2 += v * att_d[hh * C + c];
        }
#pragma unroll
        for (int o = 16; o > 0; o >>= 1) {
            s1 += __shfl_down_sync(0xffffffffu, s1, o);
            s2 += __shfl_down_sync(0xffffffffu, s2, o);
        }
        if (lane == 0) { asrc[warp * 4 + hh] = s1; adst[warp * 4 + hh] = s2; }
    }
}

__global__ void init_md_kernel(unsigned* __restrict__ m, float* __restrict__ den, int n4) {
    int i = blockIdx.x * blockDim.x + threadIdx.x;
    if (i < n4) { m[i] = 0x007FFFFFu; /* fenc(-inf) */ den[i] = 0.f; }
}

__global__ void zero_kernel(float* __restrict__ p, size_t n) {
    size_t i = (size_t)blockIdx.x * blockDim.x + threadIdx.x;
    if (i < n) p[i] = 0.f;
}

// per (edge, head): e = leaky_relu(a_src[src]+a_dst[dst]); segment max via atomicMax
__global__ void edge_max_kernel(const int* __restrict__ src, const int* __restrict__ dst,
                                const float* __restrict__ asrc, const float* __restrict__ adst,
                                float* __restrict__ ebuf, unsigned* __restrict__ m, int E) {
    int idx = blockIdx.x * blockDim.x + threadIdx.x;
    if (idx >= E * 4) return;
    int e = idx >> 2, hh = idx & 3;
    int s = src[e], d = dst[e];
    float v = asrc[s * 4 + hh] + adst[d * 4 + hh];
    v = v > 0.f ? v : 0.2f * v;
    ebuf[idx] = v;
    atomicMax(&m[d * 4 + hh], fenc(v));
}

// per (edge, head): ex = exp(e - m[dst]); segment sum via atomicAdd
__global__ void edge_exp_kernel(const int* __restrict__ dst, const unsigned* __restrict__ m,
                                float* __restrict__ ebuf, float* __restrict__ den, int E) {
    int idx = blockIdx.x * blockDim.x + threadIdx.x;
    if (idx >= E * 4) return;
    int e = idx >> 2, hh = idx & 3;
    int d = dst[e];
    float ex = expf(ebuf[idx] - fdec(m[d * 4 + hh]));
    ebuf[idx] = ex;
    atomicAdd(&den[d * 4 + hh], ex);
}

// per edge: agg[dst] += h[src] * alpha   (block of 256 threads / edge)
__global__ void edge_agg_kernel(const int* __restrict__ src, const int* __restrict__ dst,
                                const float* __restrict__ h, const float* __restrict__ ebuf,
                                const float* __restrict__ den, float* __restrict__ agg,
                                int HW, int cshift) {
    __shared__ float w[4];
    int e = blockIdx.x;
    int s = src[e], d = dst[e];
    if (threadIdx.x < 4)
        w[threadIdx.x] = ebuf[e * 4 + threadIdx.x] / (den[d * 4 + threadIdx.x] + 1e-16f);
    __syncthreads();
    const float* hs = h + (size_t)s * HW;
    float* ad = agg + (size_t)d * HW;
    for (int i = threadIdx.x; i < HW; i += blockDim.x)
        atomicAdd(&ad[i], hs[i] * w[i >> cshift]);
}

// layers 0/1: out = elu(agg + bias + lin)
__global__ void finalize_concat_kernel(const float* __restrict__ agg, const float* __restrict__ b,
                                       const float* __restrict__ lin, float* __restrict__ out,
                                       int total, int HW) {
    int idx = blockIdx.x * blockDim.x + threadIdx.x;
    if (idx >= total) return;
    int j = idx & (HW - 1);
    float v = agg[idx] + b[j] + lin[idx];
    out[idx] = v > 0.f ? v : expm1f(v);
}

// layer 2: out = mean_heads(agg) + bias + lin   (no activation)
__global__ void finalize_mean_kernel(const float* __restrict__ agg, const float* __restrict__ b,
                                     const float* __restrict__ lin, float* __restrict__ out, int n) {
    int idx = blockIdx.x * blockDim.x + threadIdx.x;
    if (idx >= n * 128) return;
    int ni = idx >> 7, j = idx & 127;
    const float* a = agg + (size_t)ni * 512;
    float v = 0.25f * (a[j] + a[128 + j] + a[256 + j] + a[384 + j]) + b[j] + lin[idx];
    out[idx] = v;
}

// ---------------- host side --------------------------------------------------
static void run_gat_layer(const float* cur, const float* W, const float* as,
                          const float* ad, const float* b, const float* lw,
                          const float* lb, int HW, int C, int linOut,
                          float* outbuf, bool last,
                          const int* src, const int* dst,
                          float* hbuf, float* linbuf, float* aggbuf,
                          float* asrcb, float* adstb, unsigned* mb, float* denb,
                          float* eb, int n, int E) {
    dim3 g1(HW / 128, (n + 127) / 128);
    sgemm_kernel<<<g1, 256>>>(cur, W, nullptr, hbuf, n, 256, HW);
    dim3 g2(linOut / 128, (n + 127) / 128);
    sgemm_kernel<<<g2, 256>>>(cur, lw, lb, linbuf, n, 256, linOut);
    attn_kernel<<<(n + 7) / 8, 256>>>(hbuf, as, ad, asrcb, adstb, n, C);
    init_md_kernel<<<(n * 4 + 255) / 256, 256>>>(mb, denb, n * 4);
    size_t aggN = (size_t)n * HW;
    zero_kernel<<<(unsigned)((aggN + 255) / 256), 256>>>(aggbuf, aggN);
    edge_max_kernel<<<(E * 4 + 255) / 256, 256>>>(src, dst, asrcb, adstb, eb, mb, E);
    edge_exp_kernel<<<(E * 4 + 255) / 256, 256>>>(dst, mb, eb, denb, E);
    int cshift = (C == 64) ? 6 : 7;
    edge_agg_kernel<<<E, 256>>>(src, dst, hbuf, eb, denb, aggbuf, HW, cshift);
    if (!last)
        finalize_concat_kernel<<<(n * HW + 255) / 256, 256>>>(aggbuf, b, linbuf, outbuf, n * HW, HW);
    else
        finalize_mean_kernel<<<(n * 128 + 255) / 256, 256>>>(aggbuf, b, linbuf, outbuf, n);
}

extern "C" void kernel_launch(void* const* d_in, const int* in_sizes, int n_in,
                              void* d_out, int out_size) {
    const float* x  = (const float*)d_in[0];
    const int*   ei = (const int*)d_in[1];
    const int n = in_sizes[0] / 256;   // 50000
    const int E = in_sizes[1] / 2;     // 300000
    const int* src = ei;
    const int* dst = ei + E;

    float *hbuf, *linbuf, *aggbuf, *b0buf, *b1buf, *asrcb, *adstb, *denb, *eb;
    unsigned* mb;
    cudaGetSymbolAddress((void**)&hbuf, g_h);
    cudaGetSymbolAddress((void**)&linbuf, g_lin);
    cudaGetSymbolAddress((void**)&aggbuf, g_agg);
    cudaGetSymbolAddress((void**)&b0buf, g_buf0);
    cudaGetSymbolAddress((void**)&b1buf, g_buf1);
    cudaGetSymbolAddress((void**)&asrcb, g_asrc);
    cudaGetSymbolAddress((void**)&adstb, g_adst);
    cudaGetSymbolAddress((void**)&mb, g_m);
    cudaGetSymbolAddress((void**)&denb, g_den);
    cudaGetSymbolAddress((void**)&eb, g_e);

    // layer 0: GATConv(256->64,h=4,concat) + Linear(256->256), elu
    run_gat_layer(x, (const float*)d_in[2], (const float*)d_in[3], (const float*)d_in[4],
                  (const float*)d_in[5], (const float*)d_in[6], (const float*)d_in[7],
                  256, 64, 256, b0buf, false, src, dst,
                  hbuf, linbuf, aggbuf, asrcb, adstb, mb, denb, eb, n, E);
    // layer 1
    run_gat_layer(b0buf, (const float*)d_in[8], (const float*)d_in[9], (const float*)d_in[10],
                  (const float*)d_in[11], (const float*)d_in[12], (const float*)d_in[13],
                  256, 64, 256, b1buf, false, src, dst,
                  hbuf, linbuf, aggbuf, asrcb, adstb, mb, denb, eb, n, E);
    // layer 2: GATConv(256->128,h=4,mean) + Linear(256->128), no activation
    run_gat_layer(b1buf, (const float*)d_in[14], (const float*)d_in[15], (const float*)d_in[16],
                  (const float*)d_in[17], (const float*)d_in[18], (const float*)d_in[19],
                  512, 128, 128, (float*)d_out, true, src, dst,
                  hbuf, linbuf, aggbuf, asrcb, adstb, mb, denb, eb, n, E);
}

// round 2
// speedup vs baseline: 1.8364x; 1.8364x over previous
#include <cuda_runtime.h>
#include <mma.h>
#include <math.h>

using namespace nvcuda;

#define NN 50000
#define NE 300000
#define NPAD (NN + 128)   // GEMM outputs padded so wmma stores never corrupt neighbors

// ---------------- scratch (device globals; no runtime allocation) ----------
__device__ float    g_h   [(size_t)NPAD * 512];
__device__ float    g_lin [(size_t)NPAD * 256];
__device__ float    g_agg [(size_t)NN * 512];
__device__ float    g_buf0[(size_t)NN * 256];
__device__ float    g_buf1[(size_t)NN * 256];
__device__ float    g_asrc[NN * 4];
__device__ float    g_adst[NN * 4];
__device__ unsigned g_m   [NN * 4];
__device__ float    g_den [NN * 4];
__device__ float    g_e   [NE * 4];
__device__ int      g_deg [NN];
__device__ int      g_rowptr[NN + 1];
__device__ int      g_cursor[NN];
__device__ int      g_eids[NE];

// ---------------- helpers ---------------------------------------------------
__device__ __forceinline__ unsigned fenc(float f) {
    unsigned u = __float_as_uint(f);
    return (u & 0x80000000u) ? ~u : (u | 0x80000000u);
}
__device__ __forceinline__ float fdec(unsigned u) {
    return (u & 0x80000000u) ? __uint_as_float(u ^ 0x80000000u)
                             : __uint_as_float(~u);
}

// ---------------- tf32 tensor-core GEMM: C[M,N] = A[M,K] @ B[K,N] -----------
// BM=BN=128, BK=32, 256 threads (8 warps, 4x2), warp tile 32x64 via wmma 16x16x8.
// M may exceed logical rows; C must be padded to a 128 multiple of rows.
#define BM 128
#define BN 128
#define BK 32

__global__ __launch_bounds__(256)
void gemm_tf32(const float* __restrict__ A, const float* __restrict__ B,
               float* __restrict__ C, int M, int K, int N) {
    __shared__ float As[BM][BK + 4];   // stride 36 floats = 144B (16B aligned)
    __shared__ float Bs[BK][BN + 4];   // stride 132 floats = 528B (16B aligned)
    const int tid  = threadIdx.x;
    const int warp = tid >> 5;
    const int wm   = warp >> 1;        // 0..3  (M)
    const int wn   = warp & 1;         // 0..1  (N)
    const int mBase = blockIdx.y * BM;
    const int nBase = blockIdx.x * BN;

    wmma::fragment<wmma::accumulator, 16, 16, 8, float> acc[2][4];
#pragma unroll
    for (int i = 0; i < 2; i++)
#pragma unroll
        for (int j = 0; j < 4; j++) wmma::fill_fragment(acc[i][j], 0.f);

    for (int k0 = 0; k0 < K; k0 += BK) {
        // load A tile: 128x32 = 1024 float4, 4 per thread
#pragma unroll
        for (int l = 0; l < 4; l++) {
            int f = tid + l * 256;
            int r = f >> 3, c = (f & 7) * 4;
            int gr = mBase + r;
            float4 v = (gr < M) ? *reinterpret_cast<const float4*>(A + (size_t)gr * K + k0 + c)
                                : make_float4(0.f, 0.f, 0.f, 0.f);
            *reinterpret_cast<float4*>(&As[r][c]) = v;
        }
        // load B tile: 32x128 = 1024 float4, 4 per thread
#pragma unroll
        for (int l = 0; l < 4; l++) {
            int f = tid + l * 256;
            int r = f >> 5, c = (f & 31) * 4;
            float4 v = *reinterpret_cast<const float4*>(B + (size_t)(k0 + r) * N + nBase + c);
            *reinterpret_cast<float4*>(&Bs[r][c]) = v;
        }
        __syncthreads();

#pragma unroll
        for (int kk = 0; kk < BK; kk += 8) {
            wmma::fragment<wmma::matrix_a, 16, 16, 8, wmma::precision::tf32, wmma::row_major> a0, a1;
            wmma::load_matrix_sync(a0, &As[wm * 32][kk], BK + 4);
            wmma::load_matrix_sync(a1, &As[wm * 32 + 16][kk], BK + 4);
#pragma unroll
            for (int t = 0; t < a0.num_elements; t++) {
                a0.x[t] = wmma::__float_to_tf32(a0.x[t]);
                a1.x[t] = wmma::__float_to_tf32(a1.x[t]);
            }
#pragma unroll
            for (int j = 0; j < 4; j++) {
                wmma::fragment<wmma::matrix_b, 16, 16, 8, wmma::precision::tf32, wmma::row_major> b;
                wmma::load_matrix_sync(b, &Bs[kk][wn * 64 + j * 16], BN + 4);
#pragma unroll
                for (int t = 0; t < b.num_elements; t++) b.x[t] = wmma::__float_to_tf32(b.x[t]);
                wmma::mma_sync(acc[0][j], a0, b, acc[0][j]);
                wmma::mma_sync(acc[1][j], a1, b, acc[1][j]);
            }
        }
        __syncthreads();
    }

#pragma unroll
    for (int i = 0; i < 2; i++)
#pragma unroll
        for (int j = 0; j < 4; j++) {
            float* Cp = C + (size_t)(mBase + wm * 32 + i * 16) * N + nBase + wn * 64 + j * 16;
            wmma::store_matrix_sync(Cp, acc[i][j], N, wmma::mem_row_major);
        }
}

// ---------------- CSR build --------------------------------------------------
__global__ void zero_int_kernel(int* __restrict__ p, int n) {
    int i = blockIdx.x * blockDim.x + threadIdx.x;
    if (i < n) p[i] = 0;
}
__global__ void count_deg_kernel(const int* __restrict__ dst, int* __restrict__ deg, int E) {
    int e = blockIdx.x * blockDim.x + threadIdx.x;
    if (e < E) atomicAdd(&deg[dst[e]], 1);
}
// single-block exclusive scan over n ints (n <= 1024 * CHUNK)
__global__ __launch_bounds__(1024)
void scan_kernel(const int* __restrict__ deg, int* __restrict__ rowptr, int n) {
    __shared__ int sums[1024];
    const int chunk = (n + 1023) / 1024;
    const int start = threadIdx.x * chunk;
    int s = 0;
    for (int i = 0; i < chunk; i++) {
        int idx = start + i;
        s += (idx < n) ? deg[idx] : 0;
    }
    sums[threadIdx.x] = s;
    __syncthreads();
    for (int off = 1; off < 1024; off <<= 1) {
        int v = 0;
        if (threadIdx.x >= off) v = sums[threadIdx.x - off];
        __syncthreads();
        if (threadIdx.x >= off) sums[threadIdx.x] += v;
        __syncthreads();
    }
    int base = (threadIdx.x == 0) ? 0 : sums[threadIdx.x - 1];
    for (int i = 0; i < chunk; i++) {
        int idx = start + i;
        if (idx < n) { rowptr[idx] = base; base += deg[idx]; }
    }
    if (threadIdx.x == 1023) rowptr[n] = sums[1023];
}
__global__ void copy_cursor_kernel(const int* __restrict__ rowptr, int* __restrict__ cursor, int n) {
    int i = blockIdx.x * blockDim.x + threadIdx.x;
    if (i < n) cursor[i] = rowptr[i];
}
__global__ void scatter_kernel(const int* __restrict__ dst, int* __restrict__ cursor,
                               int* __restrict__ eids, int E) {
    int e = blockIdx.x * blockDim.x + threadIdx.x;
    if (e < E) {
        int p = atomicAdd(&cursor[dst[e]], 1);
        eids[p] = e;
    }
}

// ---------------- per-node attention dot products ---------------------------
__global__ void attn_kernel(const float* __restrict__ h,
                            const float* __restrict__ att_s,
                            const float* __restrict__ att_d,
                            float* __restrict__ asrc, float* __restrict__ adst,
                            int n, int C) {
    int warp = (blockIdx.x * blockDim.x + threadIdx.x) >> 5;
    int lane = threadIdx.x & 31;
    if (warp >= n) return;
    const float* hr = h + (size_t)warp * 4 * C;
#pragma unroll
    for (int hh = 0; hh < 4; hh++) {
        float s1 = 0.f, s2 = 0.f;
        for (int c = lane; c < C; c += 32) {
            float v = hr[hh * C + c];
            s1 += v * att_s[hh * C + c];
            s2 += v * att_d[hh * C + c];
        }
#pragma unroll
        for (int o = 16; o > 0; o >>= 1) {
            s1 += __shfl_down_sync(0xffffffffu, s1, o);
            s2 += __shfl_down_sync(0xffffffffu, s2, o);
        }
        if (lane == 0) { asrc[warp * 4 + hh] = s1; adst[warp * 4 + hh] = s2; }
    }
}

__global__ void init_md_kernel(unsigned* __restrict__ m, float* __restrict__ den, int n4) {
    int i = blockIdx.x * blockDim.x + threadIdx.x;
    if (i < n4) { m[i] = 0x007FFFFFu; den[i] = 0.f; }
}

__global__ void edge_max_kernel(const int* __restrict__ src, const int* __restrict__ dst,
                                const float* __restrict__ asrc, const float* __restrict__ adst,
                                float* __restrict__ ebuf, unsigned* __restrict__ m, int E) {
    int idx = blockIdx.x * blockDim.x + threadIdx.x;
    if (idx >= E * 4) return;
    int e = idx >> 2, hh = idx & 3;
    int s = src[e], d = dst[e];
    float v = asrc[s * 4 + hh] + adst[d * 4 + hh];
    v = v > 0.f ? v : 0.2f * v;
    ebuf[idx] = v;
    atomicMax(&m[d * 4 + hh], fenc(v));
}

__global__ void edge_exp_kernel(const int* __restrict__ dst, const unsigned* __restrict__ m,
                                float* __restrict__ ebuf, float* __restrict__ den, int E) {
    int idx = blockIdx.x * blockDim.x + threadIdx.x;
    if (idx >= E * 4) return;
    int e = idx >> 2, hh = idx & 3;
    int d = dst[e];
    float ex = expf(ebuf[idx] - fdec(m[d * 4 + hh]));
    ebuf[idx] = ex;
    atomicAdd(&den[d * 4 + hh], ex);
}

// ---------------- CSR pull aggregation: one warp per (node, head) -----------
template <int C>
__global__ __launch_bounds__(256)
void agg_pull_kernel(const int* __restrict__ rowptr, const int* __restrict__ eids,
                     const int* __restrict__ src, const float* __restrict__ h,
                     const float* __restrict__ ebuf, const float* __restrict__ den,
                     float* __restrict__ agg, int n) {
    const int gw = blockIdx.x * 8 + (threadIdx.x >> 5);
    const int node = gw >> 2;
    const int head = gw & 3;
    if (node >= n) return;
    const int lane = threadIdx.x & 31;
    const int HW = 4 * C;
    const int beg = rowptr[node], end = rowptr[node + 1];

    float acc[C / 32];
#pragma unroll
    for (int j = 0; j < C / 32; j++) acc[j] = 0.f;

    for (int i = beg; i < end; i++) {
        int e = eids[i];
        int s = src[e];
        float w = ebuf[e * 4 + head];
        const float* hs = h + (size_t)s * HW + head * C + lane;
#pragma unroll
        for (int j = 0; j < C / 32; j++) acc[j] += w * hs[j * 32];
    }
    float dn = den[node * 4 + head] + 1e-16f;
    float inv = 1.f / dn;
    float* out = agg + (size_t)node * HW + head * C + lane;
#pragma unroll
    for (int j = 0; j < C / 32; j++) out[j * 32] = acc[j] * inv;
}

// layers 0/1: out = elu(agg + b + lin + lb)
__global__ void finalize_concat_kernel(const float* __restrict__ agg, const float* __restrict__ b,
                                       const float* __restrict__ lb, const float* __restrict__ lin,
                                       float* __restrict__ out, int total, int HW) {
    int idx = blockIdx.x * blockDim.x + threadIdx.x;
    if (idx >= total) return;
    int j = idx & (HW - 1);
    int row = idx / HW;
    float v = agg[idx] + b[j] + lin[(size_t)row * HW + j] + lb[j];
    out[idx] = v > 0.f ? v : expm1f(v);
}

// layer 2: out = mean_heads(agg) + b + lin + lb
__global__ void finalize_mean_kernel(const float* __restrict__ agg, const float* __restrict__ b,
                                     const float* __restrict__ lb, const float* __restrict__ lin,
                                     float* __restrict__ out, int n) {
    int idx = blockIdx.x * blockDim.x + threadIdx.x;
    if (idx >= n * 128) return;
    int ni = idx >> 7, j = idx & 127;
    const float* a = agg + (size_t)ni * 512;
    float v = 0.25f * (a[j] + a[128 + j] + a[256 + j] + a[384 + j])
              + b[j] + lin[(size_t)ni * 128 + j] + lb[j];
    out[idx] = v;
}

// ---------------- host side --------------------------------------------------
static void run_gat_layer(const float* cur, const float* W, const float* as,
                          const float* ad, const float* b, const float* lw,
                          const float* lb, int HW, int C, int linOut,
                          float* outbuf, bool last,
                          const int* src, const int* dst,
                          float* hbuf, float* linbuf, float* aggbuf,
                          float* asrcb, float* adstb, unsigned* mb, float* denb,
                          float* eb, const int* rowptr, const int* eids,
                          int n, int E) {
    dim3 g1(HW / 128, (n + 127) / 128);
    gemm_tf32<<<g1, 256>>>(cur, W, hbuf, n, 256, HW);
    dim3 g2(linOut / 128, (n + 127) / 128);
    gemm_tf32<<<g2, 256>>>(cur, lw, linbuf, n, 256, linOut);
    attn_kernel<<<(n + 7) / 8, 256>>>(hbuf, as, ad, asrcb, adstb, n, C);
    init_md_kernel<<<(n * 4 + 255) / 256, 256>>>(mb, denb, n * 4);
    edge_max_kernel<<<(E * 4 + 255) / 256, 256>>>(src, dst, asrcb, adstb, eb, mb, E);
    edge_exp_kernel<<<(E * 4 + 255) / 256, 256>>>(dst, mb, eb, denb, E);
    int nwarps = n * 4;
    int nblocks = (nwarps + 7) / 8;
    if (C == 64)
        agg_pull_kernel<64><<<nblocks, 256>>>(rowptr, eids, src, hbuf, eb, denb, aggbuf, n);
    else
        agg_pull_kernel<128><<<nblocks, 256>>>(rowptr, eids, src, hbuf, eb, denb, aggbuf, n);
    if (!last)
        finalize_concat_kernel<<<(n * HW + 255) / 256, 256>>>(aggbuf, b, lb, linbuf, outbuf, n * HW, HW);
    else
        finalize_mean_kernel<<<(n * 128 + 255) / 256, 256>>>(aggbuf, b, lb, linbuf, outbuf, n);
}

extern "C" void kernel_launch(void* const* d_in, const int* in_sizes, int n_in,
                              void* d_out, int out_size) {
    const float* x  = (const float*)d_in[0];
    const int*   ei = (const int*)d_in[1];
    const int n = in_sizes[0] / 256;   // 50000
    const int E = in_sizes[1] / 2;     // 300000
    const int* src = ei;
    const int* dst = ei + E;

    float *hbuf, *linbuf, *aggbuf, *b0buf, *b1buf, *asrcb, *adstb, *denb, *eb;
    unsigned* mb;
    int *deg, *rowptr, *cursor, *eids;
    cudaGetSymbolAddress((void**)&hbuf, g_h);
    cudaGetSymbolAddress((void**)&linbuf, g_lin);
    cudaGetSymbolAddress((void**)&aggbuf, g_agg);
    cudaGetSymbolAddress((void**)&b0buf, g_buf0);
    cudaGetSymbolAddress((void**)&b1buf, g_buf1);
    cudaGetSymbolAddress((void**)&asrcb, g_asrc);
    cudaGetSymbolAddress((void**)&adstb, g_adst);
    cudaGetSymbolAddress((void**)&mb, g_m);
    cudaGetSymbolAddress((void**)&denb, g_den);
    cudaGetSymbolAddress((void**)&eb, g_e);
    cudaGetSymbolAddress((void**)&deg, g_deg);
    cudaGetSymbolAddress((void**)&rowptr, g_rowptr);
    cudaGetSymbolAddress((void**)&cursor, g_cursor);
    cudaGetSymbolAddress((void**)&eids, g_eids);

    // CSR build (edge_index only; shared by all 3 layers)
    zero_int_kernel<<<(n + 255) / 256, 256>>>(deg, n);
    count_deg_kernel<<<(E + 255) / 256, 256>>>(dst, deg, E);
    scan_kernel<<<1, 1024>>>(deg, rowptr, n);
    copy_cursor_kernel<<<(n + 255) / 256, 256>>>(rowptr, cursor, n);
    scatter_kernel<<<(E + 255) / 256, 256>>>(dst, cursor, eids, E);

    run_gat_layer(x, (const float*)d_in[2], (const float*)d_in[3], (const float*)d_in[4],
                  (const float*)d_in[5], (const float*)d_in[6], (const float*)d_in[7],
                  256, 64, 256, b0buf, false, src, dst,
                  hbuf, linbuf, aggbuf, asrcb, adstb, mb, denb, eb, rowptr, eids, n, E);
    run_gat_layer(b0buf, (const float*)d_in[8], (const float*)d_in[9], (const float*)d_in[10],
                  (const float*)d_in[11], (const float*)d_in[12], (const float*)d_in[13],
                  256, 64, 256, b1buf, false, src, dst,
                  hbuf, linbuf, aggbuf, asrcb, adstb, mb, denb, eb, rowptr, eids, n, E);
    run_gat_layer(b1buf, (const float*)d_in[14], (const float*)d_in[15], (const float*)d_in[16],
                  (const float*)d_in[17], (const float*)d_in[18], (const float*)d_in[19],
                  512, 128, 128, (float*)d_out, true, src, dst,
                  hbuf, linbuf, aggbuf, asrcb, adstb, mb, denb, eb, rowptr, eids, n, E);
}

// round 3
// speedup vs baseline: 2.0524x; 1.1176x over previous
#include <cuda_runtime.h>
#include <mma.h>
#include <math.h>

using namespace nvcuda;

#define NN 50000
#define NE 300000
#define NPAD (NN + 128)   // GEMM outputs padded so unguarded tile stores are safe

// ---------------- scratch (device globals; no runtime allocation) ----------
__device__ float    g_h   [(size_t)NPAD * 512];
__device__ float    g_lin [(size_t)NPAD * 256];
__device__ float    g_agg [(size_t)NN * 512];
__device__ float    g_buf0[(size_t)NN * 256];
__device__ float    g_buf1[(size_t)NN * 256];
__device__ float    g_asrc[NN * 4];
__device__ float    g_adst[NN * 4];
__device__ unsigned g_m   [NN * 4];
__device__ float    g_den [NN * 4];
__device__ float    g_e   [NE * 4];
__device__ int      g_deg [NN];
__device__ int      g_rowptr[NN + 1];
__device__ int      g_cursor[NN];
__device__ int      g_eids[NE];

// ---------------- helpers ---------------------------------------------------
__device__ __forceinline__ unsigned fenc(float f) {
    unsigned u = __float_as_uint(f);
    return (u & 0x80000000u) ? ~u : (u | 0x80000000u);
}
__device__ __forceinline__ float fdec(unsigned u) {
    return (u & 0x80000000u) ? __uint_as_float(u ^ 0x80000000u)
                             : __uint_as_float(~u);
}

// ---------------- tf32 tensor-core GEMM (double-buffered) -------------------
// C[M,N] = A[M,K] @ B[K,N]. BM=BN=128, BK=32, 256 threads (8 warps, 4x2 tiling,
// warp tile 32x64 via wmma 16x16x8 tf32). tf32 rounding applied ONCE at smem
// store; fragment loads are raw LDS. Two smem stages, register-staged prefetch.
// Rows >= M read as zero; C rows are stored unguarded (C buffers are padded).
#define BM 128
#define BN 128
#define BK 32
#define A_LD (BK + 4)          // 36 floats  (144B, 16B aligned)
#define B_LD (BN + 4)          // 132 floats (528B, 16B aligned)
#define A_SZ (BM * A_LD)       // 4608 floats per stage
#define B_SZ (BK * B_LD)       // 4224 floats per stage
#define GEMM_SMEM ((2 * A_SZ + 2 * B_SZ) * 4)   // 70656 bytes

__global__ __launch_bounds__(256)
void gemm_tf32(const float* __restrict__ A, const float* __restrict__ B,
               float* __restrict__ C, int M, int K, int N) {
    extern __shared__ float sm[];
    float* AsBase = sm;
    float* BsBase = sm + 2 * A_SZ;

    const int tid  = threadIdx.x;
    const int warp = tid >> 5;
    const int wm   = warp >> 1;        // 0..3
    const int wn   = warp & 1;         // 0..1
    const int mBase = blockIdx.y * BM;
    const int nBase = blockIdx.x * BN;

    const int arow = tid >> 3;         // 0..31 (+32*l)
    const int acol = (tid & 7) * 4;
    const int brow = tid >> 5;         // 0..7 (+8*l)
    const int bcol = (tid & 31) * 4;

    wmma::fragment<wmma::accumulator, 16, 16, 8, float> acc[2][4];
#pragma unroll
    for (int i = 0; i < 2; i++)
#pragma unroll
        for (int j = 0; j < 4; j++) wmma::fill_fragment(acc[i][j], 0.f);

    float4 aR[4], bR[4];

    // ---- prologue: load tile 0 into registers ----
#pragma unroll
    for (int l = 0; l < 4; l++) {
        int gr = mBase + arow + 32 * l;
        aR[l] = (gr < M) ? *reinterpret_cast<const float4*>(A + (size_t)gr * K + acol)
                         : make_float4(0.f, 0.f, 0.f, 0.f);
        bR[l] = *reinterpret_cast<const float4*>(B + (size_t)(brow + 8 * l) * N + nBase + bcol);
    }
    // cvt + store stage 0
    {
        float* As = AsBase;
        float* Bs = BsBase;
#pragma unroll
        for (int l = 0; l < 4; l++) {
            float4 a = make_float4(wmma::__float_to_tf32(aR[l].x), wmma::__float_to_tf32(aR[l].y),
                                   wmma::__float_to_tf32(aR[l].z), wmma::__float_to_tf32(aR[l].w));
            *reinterpret_cast<float4*>(As + (arow + 32 * l) * A_LD + acol) = a;
            float4 b = make_float4(wmma::__float_to_tf32(bR[l].x), wmma::__float_to_tf32(bR[l].y),
                                   wmma::__float_to_tf32(bR[l].z), wmma::__float_to_tf32(bR[l].w));
            *reinterpret_cast<float4*>(Bs + (brow + 8 * l) * B_LD + bcol) = b;
        }
    }
    __syncthreads();

    int buf = 0;
    for (int k0 = BK; k0 <= K; k0 += BK) {
        const bool more = (k0 < K);
        if (more) {
#pragma unroll
            for (int l = 0; l < 4; l++) {
                int gr = mBase + arow + 32 * l;
                aR[l] = (gr < M) ? *reinterpret_cast<const float4*>(A + (size_t)gr * K + k0 + acol)
                                 : make_float4(0.f, 0.f, 0.f, 0.f);
                bR[l] = *reinterpret_cast<const float4*>(B + (size_t)(k0 + brow + 8 * l) * N + nBase + bcol);
            }
        }
        // ---- compute current stage ----
        {
            const float* As = AsBase + buf * A_SZ;
            const float* Bs = BsBase + buf * B_SZ;
#pragma unroll
            for (int kk = 0; kk < BK; kk += 8) {
                wmma::fragment<wmma::matrix_a, 16, 16, 8, wmma::precision::tf32, wmma::row_major> a0, a1;
                wmma::load_matrix_sync(a0, As + (wm * 32) * A_LD + kk, A_LD);
                wmma::load_matrix_sync(a1, As + (wm * 32 + 16) * A_LD + kk, A_LD);
#pragma unroll
                for (int j = 0; j < 4; j++) {
                    wmma::fragment<wmma::matrix_b, 16, 16, 8, wmma::precision::tf32, wmma::row_major> b;
                    wmma::load_matrix_sync(b, Bs + kk * B_LD + wn * 64 + j * 16, B_LD);
                    wmma::mma_sync(acc[0][j], a0, b, acc[0][j]);
                    wmma::mma_sync(acc[1][j], a1, b, acc[1][j]);
                }
            }
        }
        if (more) {
            float* As = AsBase + (buf ^ 1) * A_SZ;
            float* Bs = BsBase + (buf ^ 1) * B_SZ;
#pragma unroll
            for (int l = 0; l < 4; l++) {
                float4 a = make_float4(wmma::__float_to_tf32(aR[l].x), wmma::__float_to_tf32(aR[l].y),
                                       wmma::__float_to_tf32(aR[l].z), wmma::__float_to_tf32(aR[l].w));
                *reinterpret_cast<float4*>(As + (arow + 32 * l) * A_LD + acol) = a;
                float4 b = make_float4(wmma::__float_to_tf32(bR[l].x), wmma::__float_to_tf32(bR[l].y),
                                       wmma::__float_to_tf32(bR[l].z), wmma::__float_to_tf32(bR[l].w));
                *reinterpret_cast<float4*>(Bs + (brow + 8 * l) * B_LD + bcol) = b;
            }
            __syncthreads();
            buf ^= 1;
        }
    }

#pragma unroll
    for (int i = 0; i < 2; i++)
#pragma unroll
        for (int j = 0; j < 4; j++) {
            float* Cp = C + (size_t)(mBase + wm * 32 + i * 16) * N + nBase + wn * 64 + j * 16;
            wmma::store_matrix_sync(Cp, acc[i][j], N, wmma::mem_row_major);
        }
}

// ---------------- CSR build --------------------------------------------------
__global__ void zero_int_kernel(int* __restrict__ p, int n) {
    int i = blockIdx.x * blockDim.x + threadIdx.x;
    if (i < n) p[i] = 0;
}
__global__ void count_deg_kernel(const int* __restrict__ dst, int* __restrict__ deg, int E) {
    int e = blockIdx.x * blockDim.x + threadIdx.x;
    if (e < E) atomicAdd(&deg[dst[e]], 1);
}
__global__ __launch_bounds__(1024)
void scan_kernel(const int* __restrict__ deg, int* __restrict__ rowptr, int n) {
    __shared__ int sums[1024];
    const int chunk = (n + 1023) / 1024;
    const int start = threadIdx.x * chunk;
    int s = 0;
    for (int i = 0; i < chunk; i++) {
        int idx = start + i;
        s += (idx < n) ? deg[idx] : 0;
    }
    sums[threadIdx.x] = s;
    __syncthreads();
    for (int off = 1; off < 1024; off <<= 1) {
        int v = 0;
        if (threadIdx.x >= off) v = sums[threadIdx.x - off];
        __syncthreads();
        if (threadIdx.x >= off) sums[threadIdx.x] += v;
        __syncthreads();
    }
    int base = (threadIdx.x == 0) ? 0 : sums[threadIdx.x - 1];
    for (int i = 0; i < chunk; i++) {
        int idx = start + i;
        if (idx < n) { rowptr[idx] = base; base += deg[idx]; }
    }
    if (threadIdx.x == 1023) rowptr[n] = sums[1023];
}
__global__ void copy_cursor_kernel(const int* __restrict__ rowptr, int* __restrict__ cursor, int n) {
    int i = blockIdx.x * blockDim.x + threadIdx.x;
    if (i < n) cursor[i] = rowptr[i];
}
__global__ void scatter_kernel(const int* __restrict__ dst, int* __restrict__ cursor,
                               int* __restrict__ eids, int E) {
    int e = blockIdx.x * blockDim.x + threadIdx.x;
    if (e < E) {
        int p = atomicAdd(&cursor[dst[e]], 1);
        eids[p] = e;
    }
}

// ---------------- per-node attention dot products ---------------------------
__global__ void attn_kernel(const float* __restrict__ h,
                            const float* __restrict__ att_s,
                            const float* __restrict__ att_d,
                            float* __restrict__ asrc, float* __restrict__ adst,
                            int n, int C) {
    int warp = (blockIdx.x * blockDim.x + threadIdx.x) >> 5;
    int lane = threadIdx.x & 31;
    if (warp >= n) return;
    const float* hr = h + (size_t)warp * 4 * C;
#pragma unroll
    for (int hh = 0; hh < 4; hh++) {
        float s1 = 0.f, s2 = 0.f;
        for (int c = lane; c < C; c += 32) {
            float v = hr[hh * C + c];
            s1 += v * att_s[hh * C + c];
            s2 += v * att_d[hh * C + c];
        }
#pragma unroll
        for (int o = 16; o > 0; o >>= 1) {
            s1 += __shfl_down_sync(0xffffffffu, s1, o);
            s2 += __shfl_down_sync(0xffffffffu, s2, o);
        }
        if (lane == 0) { asrc[warp * 4 + hh] = s1; adst[warp * 4 + hh] = s2; }
    }
}

__global__ void init_md_kernel(unsigned* __restrict__ m, float* __restrict__ den, int n4) {
    int i = blockIdx.x * blockDim.x + threadIdx.x;
    if (i < n4) { m[i] = 0x007FFFFFu; den[i] = 0.f; }
}

__global__ void edge_max_kernel(const int* __restrict__ src, const int* __restrict__ dst,
                                const float* __restrict__ asrc, const float* __restrict__ adst,
                                float* __restrict__ ebuf, unsigned* __restrict__ m, int E) {
    int idx = blockIdx.x * blockDim.x + threadIdx.x;
    if (idx >= E * 4) return;
    int e = idx >> 2, hh = idx & 3;
    int s = src[e], d = dst[e];
    float v = asrc[s * 4 + hh] + adst[d * 4 + hh];
    v = v > 0.f ? v : 0.2f * v;
    ebuf[idx] = v;
    atomicMax(&m[d * 4 + hh], fenc(v));
}

__global__ void edge_exp_kernel(const int* __restrict__ dst, const unsigned* __restrict__ m,
                                float* __restrict__ ebuf, float* __restrict__ den, int E) {
    int idx = blockIdx.x * blockDim.x + threadIdx.x;
    if (idx >= E * 4) return;
    int e = idx >> 2, hh = idx & 3;
    int d = dst[e];
    float ex = expf(ebuf[idx] - fdec(m[d * 4 + hh]));
    ebuf[idx] = ex;
    atomicAdd(&den[d * 4 + hh], ex);
}

// ---------------- CSR pull aggregation: one warp per (node, head) -----------
template <int C>
__global__ __launch_bounds__(256)
void agg_pull_kernel(const int* __restrict__ rowptr, const int* __restrict__ eids,
                     const int* __restrict__ src, const float* __restrict__ h,
                     const float* __restrict__ ebuf, const float* __restrict__ den,
                     float* __restrict__ agg, int n) {
    const int gw = blockIdx.x * 8 + (threadIdx.x >> 5);
    const int node = gw >> 2;
    const int head = gw & 3;
    if (node >= n) return;
    const int lane = threadIdx.x & 31;
    const int HW = 4 * C;
    const int beg = rowptr[node], end = rowptr[node + 1];

    float acc[C / 32];
#pragma unroll
    for (int j = 0; j < C / 32; j++) acc[j] = 0.f;

    for (int i = beg; i < end; i++) {
        int e = eids[i];
        int s = src[e];
        float w = ebuf[e * 4 + head];
        const float* hs = h + (size_t)s * HW + head * C + lane;
#pragma unroll
        for (int j = 0; j < C / 32; j++) acc[j] += w * hs[j * 32];
    }
    float inv = 1.f / (den[node * 4 + head] + 1e-16f);
    float* out = agg + (size_t)node * HW + head * C + lane;
#pragma unroll
    for (int j = 0; j < C / 32; j++) out[j * 32] = acc[j] * inv;
}

// layers 0/1: out = elu(agg + b + lin + lb)
__global__ void finalize_concat_kernel(const float* __restrict__ agg, const float* __restrict__ b,
                                       const float* __restrict__ lb, const float* __restrict__ lin,
                                       float* __restrict__ out, int total, int HW) {
    int idx = blockIdx.x * blockDim.x + threadIdx.x;
    if (idx >= total) return;
    int j = idx & (HW - 1);
    int row = idx / HW;
    float v = agg[idx] + b[j] + lin[(size_t)row * HW + j] + lb[j];
    out[idx] = v > 0.f ? v : expm1f(v);
}

// layer 2: out = mean_heads(agg) + b + lin + lb
__global__ void finalize_mean_kernel(const float* __restrict__ agg, const float* __restrict__ b,
                                     const float* __restrict__ lb, const float* __restrict__ lin,
                                     float* __restrict__ out, int n) {
    int idx = blockIdx.x * blockDim.x + threadIdx.x;
    if (idx >= n * 128) return;
    int ni = idx >> 7, j = idx & 127;
    const float* a = agg + (size_t)ni * 512;
    float v = 0.25f * (a[j] + a[128 + j] + a[256 + j] + a[384 + j])
              + b[j] + lin[(size_t)ni * 128 + j] + lb[j];
    out[idx] = v;
}

// ---------------- host side --------------------------------------------------
static void run_gat_layer(const float* cur, const float* W, const float* as,
                          const float* ad, const float* b, const float* lw,
                          const float* lb, int HW, int C, int linOut,
                          float* outbuf, bool last,
                          const int* src, const int* dst,
                          float* hbuf, float* linbuf, float* aggbuf,
                          float* asrcb, float* adstb, unsigned* mb, float* denb,
                          float* eb, const int* rowptr, const int* eids,
                          int n, int E) {
    dim3 g1(HW / 128, (n + 127) / 128);
    gemm_tf32<<<g1, 256, GEMM_SMEM>>>(cur, W, hbuf, n, 256, HW);
    dim3 g2(linOut / 128, (n + 127) / 128);
    gemm_tf32<<<g2, 256, GEMM_SMEM>>>(cur, lw, linbuf, n, 256, linOut);
    attn_kernel<<<(n + 7) / 8, 256>>>(hbuf, as, ad, asrcb, adstb, n, C);
    init_md_kernel<<<(n * 4 + 255) / 256, 256>>>(mb, denb, n * 4);
    edge_max_kernel<<<(E * 4 + 255) / 256, 256>>>(src, dst, asrcb, adstb, eb, mb, E);
    edge_exp_kernel<<<(E * 4 + 255) / 256, 256>>>(dst, mb, eb, denb, E);
    int nblocks = (n * 4 + 7) / 8;
    if (C == 64)
        agg_pull_kernel<64><<<nblocks, 256>>>(rowptr, eids, src, hbuf, eb, denb, aggbuf, n);
    else
        agg_pull_kernel<128><<<nblocks, 256>>>(rowptr, eids, src, hbuf, eb, denb, aggbuf, n);
    if (!last)
        finalize_concat_kernel<<<(n * HW + 255) / 256, 256>>>(aggbuf, b, lb, linbuf, outbuf, n * HW, HW);
    else
        finalize_mean_kernel<<<(n * 128 + 255) / 256, 256>>>(aggbuf, b, lb, linbuf, outbuf, n);
}

extern "C" void kernel_launch(void* const* d_in, const int* in_sizes, int n_in,
                              void* d_out, int out_size) {
    const float* x  = (const float*)d_in[0];
    const int*   ei = (const int*)d_in[1];
    const int n = in_sizes[0] / 256;   // 50000
    const int E = in_sizes[1] / 2;     // 300000
    const int* src = ei;
    const int* dst = ei + E;

    static bool attr_done = false;
    if (!attr_done) {
        cudaFuncSetAttribute(gemm_tf32, cudaFuncAttributeMaxDynamicSharedMemorySize, GEMM_SMEM);
        attr_done = true;
    }

    float *hbuf, *linbuf, *aggbuf, *b0buf, *b1buf, *asrcb, *adstb, *denb, *eb;
    unsigned* mb;
    int *deg, *rowptr, *cursor, *eids;
    cudaGetSymbolAddress((void**)&hbuf, g_h);
    cudaGetSymbolAddress((void**)&linbuf, g_lin);
    cudaGetSymbolAddress((void**)&aggbuf, g_agg);
    cudaGetSymbolAddress((void**)&b0buf, g_buf0);
    cudaGetSymbolAddress((void**)&b1buf, g_buf1);
    cudaGetSymbolAddress((void**)&asrcb, g_asrc);
    cudaGetSymbolAddress((void**)&adstb, g_adst);
    cudaGetSymbolAddress((void**)&mb, g_m);
    cudaGetSymbolAddress((void**)&denb, g_den);
    cudaGetSymbolAddress((void**)&eb, g_e);
    cudaGetSymbolAddress((void**)&deg, g_deg);
    cudaGetSymbolAddress((void**)&rowptr, g_rowptr);
    cudaGetSymbolAddress((void**)&cursor, g_cursor);
    cudaGetSymbolAddress((void**)&eids, g_eids);

    // CSR build (edge_index only; shared by all 3 layers)
    zero_int_kernel<<<(n + 255) / 256, 256>>>(deg, n);
    count_deg_kernel<<<(E + 255) / 256, 256>>>(dst, deg, E);
    scan_kernel<<<1, 1024>>>(deg, rowptr, n);
    copy_cursor_kernel<<<(n + 255) / 256, 256>>>(rowptr, cursor, n);
    scatter_kernel<<<(E + 255) / 256, 256>>>(dst, cursor, eids, E);

    run_gat_layer(x, (const float*)d_in[2], (const float*)d_in[3], (const float*)d_in[4],
                  (const float*)d_in[5], (const float*)d_in[6], (const float*)d_in[7],
                  256, 64, 256, b0buf, false, src, dst,
                  hbuf, linbuf, aggbuf, asrcb, adstb, mb, denb, eb, rowptr, eids, n, E);
    run_gat_layer(b0buf, (const float*)d_in[8], (const float*)d_in[9], (const float*)d_in[10],
                  (const float*)d_in[11], (const float*)d_in[12], (const float*)d_in[13],
                  256, 64, 256, b1buf, false, src, dst,
                  hbuf, linbuf, aggbuf, asrcb, adstb, mb, denb, eb, rowptr, eids, n, E);
    run_gat_layer(b1buf, (const float*)d_in[14], (const float*)d_in[15], (const float*)d_in[16],
                  (const float*)d_in[17], (const float*)d_in[18], (const float*)d_in[19],
                  512, 128, 128, (float*)d_out, true, src, dst,
                  hbuf, linbuf, aggbuf, asrcb, adstb, mb, denb, eb, rowptr, eids, n, E);
}

// round 5
// speedup vs baseline: 2.6602x; 1.2961x over previous
#include <cuda_runtime.h>
#include <math.h>
#include <cstdint>

#define NN 50000
#define NE 300000
#define NPAD (NN + 128)

// ---------------- scratch (device globals; no runtime allocation) ----------
__device__ float    g_h   [(size_t)NPAD * 512];
__device__ float    g_lin [(size_t)NPAD * 256];
__device__ float    g_agg [(size_t)NN * 512];
__device__ float    g_buf0[(size_t)NN * 256];
__device__ float    g_buf1[(size_t)NN * 256];
__device__ float    g_asrc[NN * 4];
__device__ float    g_adst[NN * 4];
__device__ unsigned g_m   [NN * 4];
__device__ float    g_den [NN * 4];
__device__ float    g_e   [NE * 4];
__device__ int      g_deg [NN];
__device__ int      g_rowptr[NN + 1];
__device__ int      g_cursor[NN];
__device__ int      g_eids[NE];
__device__ float    g_wt  [425984];   // transposed (tf32-rounded) weights

// ---------------- helpers ---------------------------------------------------
__device__ __forceinline__ float to_tf32(float f) {
    float o;
    asm("cvt.rna.tf32.f32 %0, %1;" : "=f"(o) : "f"(f));
    return o;
}
__device__ __forceinline__ void mma_tf32(float* c, const uint4& a, const uint2& b) {
    asm volatile(
        "mma.sync.aligned.m16n8k8.row.col.f32.tf32.tf32.f32 "
        "{%0,%1,%2,%3}, {%4,%5,%6,%7}, {%8,%9}, {%0,%1,%2,%3};"
        : "+f"(c[0]), "+f"(c[1]), "+f"(c[2]), "+f"(c[3])
        : "r"(a.x), "r"(a.y), "r"(a.z), "r"(a.w), "r"(b.x), "r"(b.y));
}
__device__ __forceinline__ unsigned fenc(float f) {
    unsigned u = __float_as_uint(f);
    return (u & 0x80000000u) ? ~u : (u | 0x80000000u);
}
__device__ __forceinline__ float fdec(unsigned u) {
    return (u & 0x80000000u) ? __uint_as_float(u ^ 0x80000000u)
                             : __uint_as_float(~u);
}

// ---------------- tf32 mma.sync GEMM (fragment-packed smem) -----------------
// C[M,N] = A[M,K=256] @ Bt^T. Bt is [N,K] row-major, tf32-pre-rounded.
// Block 128x128, BK=32, 256 threads, 8 warps (4x2), warp tile 32x64.
// Smem per stage: A packed [8 mt][4 kt][32 lane][4 regs] = 16KB,
//                 B packed [16 nt][4 kt][32 lane][2 regs] = 16KB. 2 stages = 64KB.
// A fragment load = LDS.128, B fragment = LDS.64, both conflict-free.
#define GM_SMEM 65536

__global__ __launch_bounds__(256)
void gemm_mma(const float* __restrict__ A, const float* __restrict__ Bt,
              float* __restrict__ C, int M, int N) {
    extern __shared__ float sm[];
    // stage s: A at sm + s*4096, B at sm + 8192 + s*4096
    const int K = 256;
    const int tid = threadIdx.x, lane = tid & 31, warp = tid >> 5;
    const int wm = warp >> 1, wn = warp & 1;
    const int mBase = blockIdx.y * 128;
    const int nBase = blockIdx.x * 128;

    float acc[2][8][4];
#pragma unroll
    for (int i = 0; i < 2; i++)
#pragma unroll
        for (int j = 0; j < 8; j++)
#pragma unroll
            for (int r = 0; r < 4; r++) acc[i][j][r] = 0.f;

    // global-load / smem-store indexing (constant across k-chunks)
    const int rowb = tid >> 3;          // + 32*l
    const int c4   = (tid & 7) * 4;     // k offset within chunk
    const int kt   = c4 >> 3;
    const int hi   = (c4 >> 2) & 1;
    int dstA[4], dstB[4];
#pragma unroll
    for (int l = 0; l < 4; l++) {
        int row = rowb + 32 * l;
        int mt = row >> 4, rr = row & 15;
        dstA[l] = (((mt * 4 + kt) * 32) + (rr & 7) * 4) * 4 + (rr >> 3) + hi * 2;
        int nt = row >> 3, rn = row & 7;
        dstB[l] = (((nt * 4 + kt) * 32) + rn * 4) * 2 + hi;
    }

    float4 aR[4], bR[4];
#pragma unroll
    for (int l = 0; l < 4; l++) {
        int gr = mBase + rowb + 32 * l;
        aR[l] = (gr < M) ? *reinterpret_cast<const float4*>(A + (size_t)gr * K + c4)
                         : make_float4(0.f, 0.f, 0.f, 0.f);
        bR[l] = *reinterpret_cast<const float4*>(Bt + (size_t)(nBase + rowb + 32 * l) * K + c4);
    }
    // store stage 0
    {
        float* As = sm;
        float* Bs = sm + 8192;
#pragma unroll
        for (int l = 0; l < 4; l++) {
            As[dstA[l]]      = to_tf32(aR[l].x);
            As[dstA[l] + 4]  = to_tf32(aR[l].y);
            As[dstA[l] + 8]  = to_tf32(aR[l].z);
            As[dstA[l] + 12] = to_tf32(aR[l].w);
            Bs[dstB[l]]      = bR[l].x;
            Bs[dstB[l] + 2]  = bR[l].y;
            Bs[dstB[l] + 4]  = bR[l].z;
            Bs[dstB[l] + 6]  = bR[l].w;
        }
    }
    __syncthreads();

    int buf = 0;
    for (int k0 = 32; k0 <= K; k0 += 32) {
        const bool more = (k0 < K);
        if (more) {
#pragma unroll
            for (int l = 0; l < 4; l++) {
                int gr = mBase + rowb + 32 * l;
                aR[l] = (gr < M) ? *reinterpret_cast<const float4*>(A + (size_t)gr * K + k0 + c4)
                                 : make_float4(0.f, 0.f, 0.f, 0.f);
                bR[l] = *reinterpret_cast<const float4*>(Bt + (size_t)(nBase + rowb + 32 * l) * K + k0 + c4);
            }
        }
        // compute current stage
        {
            const float* As = sm + buf * 4096;
            const float* Bs = sm + 8192 + buf * 4096;
#pragma unroll
            for (int k = 0; k < 4; k++) {
                uint4 a0 = *reinterpret_cast<const uint4*>(As + ((wm * 2 + 0) * 4 + k) * 128 + lane * 4);
                uint4 a1 = *reinterpret_cast<const uint4*>(As + ((wm * 2 + 1) * 4 + k) * 128 + lane * 4);
#pragma unroll
                for (int j = 0; j < 8; j++) {
                    uint2 b = *reinterpret_cast<const uint2*>(Bs + ((wn * 8 + j) * 4 + k) * 64 + lane * 2);
                    mma_tf32(acc[0][j], a0, b);
                    mma_tf32(acc[1][j], a1, b);
                }
            }
        }
        if (more) {
            float* As = sm + (buf ^ 1) * 4096;
            float* Bs = sm + 8192 + (buf ^ 1) * 4096;
#pragma unroll
            for (int l = 0; l < 4; l++) {
                As[dstA[l]]      = to_tf32(aR[l].x);
                As[dstA[l] + 4]  = to_tf32(aR[l].y);
                As[dstA[l] + 8]  = to_tf32(aR[l].z);
                As[dstA[l] + 12] = to_tf32(aR[l].w);
                Bs[dstB[l]]      = bR[l].x;
                Bs[dstB[l] + 2]  = bR[l].y;
                Bs[dstB[l] + 4]  = bR[l].z;
                Bs[dstB[l] + 6]  = bR[l].w;
            }
            __syncthreads();
            buf ^= 1;
        }
    }

    // epilogue: direct float2 stores (C padded to NPAD rows; no row guard)
#pragma unroll
    for (int i = 0; i < 2; i++) {
        int r0 = mBase + wm * 32 + i * 16 + (lane >> 2);
#pragma unroll
        for (int j = 0; j < 8; j++) {
            int cc = nBase + wn * 64 + j * 8 + (lane & 3) * 2;
            *reinterpret_cast<float2*>(C + (size_t)r0 * N + cc) =
                make_float2(acc[i][j][0], acc[i][j][1]);
            *reinterpret_cast<float2*>(C + (size_t)(r0 + 8) * N + cc) =
                make_float2(acc[i][j][2], acc[i][j][3]);
        }
    }
}

// ---------------- weight transpose (+tf32 round) ----------------------------
__global__ void transpose_cvt(const float* __restrict__ W, float* __restrict__ Wt,
                              int K, int N) {
    __shared__ float t[32][33];
    int kb = blockIdx.y * 32, nb = blockIdx.x * 32;
    for (int i = threadIdx.y; i < 32; i += 8)
        t[i][threadIdx.x] = W[(size_t)(kb + i) * N + nb + threadIdx.x];
    __syncthreads();
    for (int i = threadIdx.y; i < 32; i += 8)
        Wt[(size_t)(nb + i) * K + kb + threadIdx.x] = to_tf32(t[threadIdx.x][i]);
}

// ---------------- CSR build --------------------------------------------------
__global__ void zero_int_kernel(int* __restrict__ p, int n) {
    int i = blockIdx.x * blockDim.x + threadIdx.x;
    if (i < n) p[i] = 0;
}
__global__ void count_deg_kernel(const int* __restrict__ dst, int* __restrict__ deg, int E) {
    int e = blockIdx.x * blockDim.x + threadIdx.x;
    if (e < E) atomicAdd(&deg[dst[e]], 1);
}
__global__ __launch_bounds__(1024)
void scan_kernel(const int* __restrict__ deg, int* __restrict__ rowptr, int n) {
    __shared__ int sums[1024];
    const int chunk = (n + 1023) / 1024;
    const int start = threadIdx.x * chunk;
    int s = 0;
    for (int i = 0; i < chunk; i++) {
        int idx = start + i;
        s += (idx < n) ? deg[idx] : 0;
    }
    sums[threadIdx.x] = s;
    __syncthreads();
    for (int off = 1; off < 1024; off <<= 1) {
        int v = 0;
        if (threadIdx.x >= off) v = sums[threadIdx.x - off];
        __syncthreads();
        if (threadIdx.x >= off) sums[threadIdx.x] += v;
        __syncthreads();
    }
    int base = (threadIdx.x == 0) ? 0 : sums[threadIdx.x - 1];
    for (int i = 0; i < chunk; i++) {
        int idx = start + i;
        if (idx < n) { rowptr[idx] = base; base += deg[idx]; }
    }
    if (threadIdx.x == 1023) rowptr[n] = sums[1023];
}
__global__ void copy_cursor_kernel(const int* __restrict__ rowptr, int* __restrict__ cursor, int n) {
    int i = blockIdx.x * blockDim.x + threadIdx.x;
    if (i < n) cursor[i] = rowptr[i];
}
__global__ void scatter_kernel(const int* __restrict__ dst, int* __restrict__ cursor,
                               int* __restrict__ eids, int E) {
    int e = blockIdx.x * blockDim.x + threadIdx.x;
    if (e < E) {
        int p = atomicAdd(&cursor[dst[e]], 1);
        eids[p] = e;
    }
}

// ---------------- edge / softmax / aggregation -------------------------------
__global__ void attn_kernel(const float* __restrict__ h,
                            const float* __restrict__ att_s,
                            const float* __restrict__ att_d,
                            float* __restrict__ asrc, float* __restrict__ adst,
                            int n, int C) {
    int warp = (blockIdx.x * blockDim.x + threadIdx.x) >> 5;
    int lane = threadIdx.x & 31;
    if (warp >= n) return;
    const float* hr = h + (size_t)warp * 4 * C;
#pragma unroll
    for (int hh = 0; hh < 4; hh++) {
        float s1 = 0.f, s2 = 0.f;
        for (int c = lane; c < C; c += 32) {
            float v = hr[hh * C + c];
            s1 += v * att_s[hh * C + c];
            s2 += v * att_d[hh * C + c];
        }
#pragma unroll
        for (int o = 16; o > 0; o >>= 1) {
            s1 += __shfl_down_sync(0xffffffffu, s1, o);
            s2 += __shfl_down_sync(0xffffffffu, s2, o);
        }
        if (lane == 0) { asrc[warp * 4 + hh] = s1; adst[warp * 4 + hh] = s2; }
    }
}

__global__ void init_md_kernel(unsigned* __restrict__ m, float* __restrict__ den, int n4) {
    int i = blockIdx.x * blockDim.x + threadIdx.x;
    if (i < n4) { m[i] = 0x007FFFFFu; den[i] = 0.f; }
}

__global__ void edge_max_kernel(const int* __restrict__ src, const int* __restrict__ dst,
                                const float* __restrict__ asrc, const float* __restrict__ adst,
                                float* __restrict__ ebuf, unsigned* __restrict__ m, int E) {
    int idx = blockIdx.x * blockDim.x + threadIdx.x;
    if (idx >= E * 4) return;
    int e = idx >> 2, hh = idx & 3;
    int s = src[e], d = dst[e];
    float v = asrc[s * 4 + hh] + adst[d * 4 + hh];
    v = v > 0.f ? v : 0.2f * v;
    ebuf[idx] = v;
    atomicMax(&m[d * 4 + hh], fenc(v));
}

__global__ void edge_exp_kernel(const int* __restrict__ dst, const unsigned* __restrict__ m,
                                float* __restrict__ ebuf, float* __restrict__ den, int E) {
    int idx = blockIdx.x * blockDim.x + threadIdx.x;
    if (idx >= E * 4) return;
    int e = idx >> 2, hh = idx & 3;
    int d = dst[e];
    float ex = expf(ebuf[idx] - fdec(m[d * 4 + hh]));
    ebuf[idx] = ex;
    atomicAdd(&den[d * 4 + hh], ex);
}

template <int C>
__global__ __launch_bounds__(256)
void agg_pull_kernel(const int* __restrict__ rowptr, const int* __restrict__ eids,
                     const int* __restrict__ src, const float* __restrict__ h,
                     const float* __restrict__ ebuf, const float* __restrict__ den,
                     float* __restrict__ agg, int n) {
    const int gw = blockIdx.x * 8 + (threadIdx.x >> 5);
    const int node = gw >> 2;
    const int head = gw & 3;
    if (node >= n) return;
    const int lane = threadIdx.x & 31;
    const int HW = 4 * C;
    const int beg = rowptr[node], end = rowptr[node + 1];

    float acc[C / 32];
#pragma unroll
    for (int j = 0; j < C / 32; j++) acc[j] = 0.f;

    for (int i = beg; i < end; i++) {
        int e = eids[i];
        int s = src[e];
        float w = ebuf[e * 4 + head];
        const float* hs = h + (size_t)s * HW + head * C + lane;
#pragma unroll
        for (int j = 0; j < C / 32; j++) acc[j] += w * hs[j * 32];
    }
    float inv = 1.f / (den[node * 4 + head] + 1e-16f);
    float* out = agg + (size_t)node * HW + head * C + lane;
#pragma unroll
    for (int j = 0; j < C / 32; j++) out[j * 32] = acc[j] * inv;
}

__global__ void finalize_concat_kernel(const float* __restrict__ agg, const float* __restrict__ b,
                                       const float* __restrict__ lb, const float* __restrict__ lin,
                                       float* __restrict__ out, int total, int HW) {
    int idx = blockIdx.x * blockDim.x + threadIdx.x;
    if (idx >= total) return;
    int j = idx & (HW - 1);
    int row = idx / HW;
    float v = agg[idx] + b[j] + lin[(size_t)row * HW + j] + lb[j];
    out[idx] = v > 0.f ? v : expm1f(v);
}

__global__ void finalize_mean_kernel(const float* __restrict__ agg, const float* __restrict__ b,
                                     const float* __restrict__ lb, const float* __restrict__ lin,
                                     float* __restrict__ out, int n) {
    int idx = blockIdx.x * blockDim.x + threadIdx.x;
    if (idx >= n * 128) return;
    int ni = idx >> 7, j = idx & 127;
    const float* a = agg + (size_t)ni * 512;
    float v = 0.25f * (a[j] + a[128 + j] + a[256 + j] + a[384 + j])
              + b[j] + lin[(size_t)ni * 128 + j] + lb[j];
    out[idx] = v;
}

// ---------------- host side --------------------------------------------------
static void run_layer_rest(const float* hbuf, const float* as, const float* ad,
                           const float* b, const float* lb, const float* linbuf,
                           int HW, int C, float* outbuf, bool last,
                           const int* src, const int* dst,
                           float* aggbuf, float* asrcb, float* adstb,
                           unsigned* mb, float* denb, float* eb,
                           const int* rowptr, const int* eids, int n, int E) {
    attn_kernel<<<(n + 7) / 8, 256>>>(hbuf, as, ad, asrcb, adstb, n, C);
    init_md_kernel<<<(n * 4 + 255) / 256, 256>>>(mb, denb, n * 4);
    edge_max_kernel<<<(E * 4 + 255) / 256, 256>>>(src, dst, asrcb, adstb, eb, mb, E);
    edge_exp_kernel<<<(E * 4 + 255) / 256, 256>>>(dst, mb, eb, denb, E);
    int nblocks = (n * 4 + 7) / 8;
    if (C == 64)
        agg_pull_kernel<64><<<nblocks, 256>>>(rowptr, eids, src, hbuf, eb, denb, aggbuf, n);
    else
        agg_pull_kernel<128><<<nblocks, 256>>>(rowptr, eids, src, hbuf, eb, denb, aggbuf, n);
    if (!last)
        finalize_concat_kernel<<<(n * HW + 255) / 256, 256>>>(aggbuf, b, lb, linbuf, outbuf, n * HW, HW);
    else
        finalize_mean_kernel<<<(n * 128 + 255) / 256, 256>>>(aggbuf, b, lb, linbuf, outbuf, n);
}

extern "C" void kernel_launch(void* const* d_in, const int* in_sizes, int n_in,
                              void* d_out, int out_size) {
    const float* x  = (const float*)d_in[0];
    const int*   ei = (const int*)d_in[1];
    const int n = in_sizes[0] / 256;   // 50000
    const int E = in_sizes[1] / 2;     // 300000
    const int* src = ei;
    const int* dst = ei + E;

    cudaFuncSetAttribute(gemm_mma, cudaFuncAttributeMaxDynamicSharedMemorySize, GM_SMEM);

    float *hbuf, *linbuf, *aggbuf, *b0buf, *b1buf, *asrcb, *adstb, *denb, *eb, *wt;
    unsigned* mb;
    int *deg, *rowptr, *cursor, *eids;
    cudaGetSymbolAddress((void**)&hbuf, g_h);
    cudaGetSymbolAddress((void**)&linbuf, g_lin);
    cudaGetSymbolAddress((void**)&aggbuf, g_agg);
    cudaGetSymbolAddress((void**)&b0buf, g_buf0);
    cudaGetSymbolAddress((void**)&b1buf, g_buf1);
    cudaGetSymbolAddress((void**)&asrcb, g_asrc);
    cudaGetSymbolAddress((void**)&adstb, g_adst);
    cudaGetSymbolAddress((void**)&mb, g_m);
    cudaGetSymbolAddress((void**)&denb, g_den);
    cudaGetSymbolAddress((void**)&eb, g_e);
    cudaGetSymbolAddress((void**)&deg, g_deg);
    cudaGetSymbolAddress((void**)&rowptr, g_rowptr);
    cudaGetSymbolAddress((void**)&cursor, g_cursor);
    cudaGetSymbolAddress((void**)&eids, g_eids);
    cudaGetSymbolAddress((void**)&wt, g_wt);

    float* wt0  = wt;             // 256x256
    float* lwt0 = wt + 65536;
    float* wt1  = wt + 131072;
    float* lwt1 = wt + 196608;
    float* wt2  = wt + 262144;    // 512x256
    float* lwt2 = wt + 393216;    // 128x256

    const int gy = (n + 127) / 128;   // 391
    dim3 tb(32, 8);

    // ordered so the 4th launch (the ncu capture slot) is the big GEMM
    transpose_cvt<<<dim3(8, 8), tb>>>((const float*)d_in[2], wt0, 256, 256);
    transpose_cvt<<<dim3(8, 8), tb>>>((const float*)d_in[6], lwt0, 256, 256);
    zero_int_kernel<<<(n + 255) / 256, 256>>>(deg, n);
    gemm_mma<<<dim3(2, gy), 256, GM_SMEM>>>(x, wt0, hbuf, n, 256);          // 4th
    gemm_mma<<<dim3(2, gy), 256, GM_SMEM>>>(x, lwt0, linbuf, n, 256);
    count_deg_kernel<<<(E + 255) / 256, 256>>>(dst, deg, E);
    scan_kernel<<<1, 1024>>>(deg, rowptr, n);
    copy_cursor_kernel<<<(n + 255) / 256, 256>>>(rowptr, cursor, n);
    scatter_kernel<<<(E + 255) / 256, 256>>>(dst, cursor, eids, E);
    transpose_cvt<<<dim3(8, 8), tb>>>((const float*)d_in[8], wt1, 256, 256);
    transpose_cvt<<<dim3(8, 8), tb>>>((const float*)d_in[12], lwt1, 256, 256);
    transpose_cvt<<<dim3(16, 8), tb>>>((const float*)d_in[14], wt2, 256, 512);
    transpose_cvt<<<dim3(4, 8), tb>>>((const float*)d_in[18], lwt2, 256, 128);

    // layer 0
    run_layer_rest(hbuf, (const float*)d_in[3], (const float*)d_in[4],
                   (const float*)d_in[5], (const float*)d_in[7], linbuf,
                   256, 64, b0buf, false, src, dst, aggbuf, asrcb, adstb,
                   mb, denb, eb, rowptr, eids, n, E);
    // layer 1
    gemm_mma<<<dim3(2, gy), 256, GM_SMEM>>>(b0buf, wt1, hbuf, n, 256);
    gemm_mma<<<dim3(2, gy), 256, GM_SMEM>>>(b0buf, lwt1, linbuf, n, 256);
    run_layer_rest(hbuf, (const float*)d_in[9], (const float*)d_in[10],
                   (const float*)d_in[11], (const float*)d_in[13], linbuf,
                   256, 64, b1buf, false, src, dst, aggbuf, asrcb, adstb,
                   mb, denb, eb, rowptr, eids, n, E);
    // layer 2
    gemm_mma<<<dim3(4, gy), 256, GM_SMEM>>>(b1buf, wt2, hbuf, n, 512);
    gemm_mma<<<dim3(1, gy), 256, GM_SMEM>>>(b1buf, lwt2, linbuf, n, 128);
    run_layer_rest(hbuf, (const float*)d_in[15], (const float*)d_in[16],
                   (const float*)d_in[17], (const float*)d_in[19], linbuf,
                   512, 128, (float*)d_out, true, src, dst, aggbuf, asrcb, adstb,
                   mb, denb, eb, rowptr, eids, n, E);
}

// round 6
// speedup vs baseline: 2.7988x; 1.0521x over previous
#include <cuda_runtime.h>
#include <math.h>
#include <cstdint>

#define NN 50000
#define NE 300000
#define NPAD (NN + 128)

// ---------------- scratch (device globals; no runtime allocation) ----------
__device__ float    g_h   [(size_t)NPAD * 512];
__device__ float    g_lin [(size_t)NPAD * 256];
__device__ float    g_agg [(size_t)NN * 512];
__device__ float    g_buf0[(size_t)NN * 256];
__device__ float    g_buf1[(size_t)NN * 256];
__device__ float    g_asrc[NN * 4];
__device__ float    g_adst[NN * 4];
__device__ unsigned g_m   [NN * 4];
__device__ float    g_den [NN * 4];
__device__ float    g_e   [NE * 4];
__device__ int      g_deg [NN];
__device__ int      g_rowptr[NN + 1];
__device__ int      g_cursor[NN];
__device__ int      g_eids[NE];
__device__ float    g_wt  [425984];   // transposed (tf32-rounded) weights

// ---------------- helpers ---------------------------------------------------
__device__ __forceinline__ float to_tf32(float f) {
    float o;
    asm("cvt.rna.tf32.f32 %0, %1;" : "=f"(o) : "f"(f));
    return o;
}
__device__ __forceinline__ void mma_tf32(float* c, const uint4& a, uint32_t b0, uint32_t b1) {
    asm volatile(
        "mma.sync.aligned.m16n8k8.row.col.f32.tf32.tf32.f32 "
        "{%0,%1,%2,%3}, {%4,%5,%6,%7}, {%8,%9}, {%0,%1,%2,%3};"
        : "+f"(c[0]), "+f"(c[1]), "+f"(c[2]), "+f"(c[3])
        : "r"(a.x), "r"(a.y), "r"(a.z), "r"(a.w), "r"(b0), "r"(b1));
}
__device__ __forceinline__ unsigned fenc(float f) {
    unsigned u = __float_as_uint(f);
    return (u & 0x80000000u) ? ~u : (u | 0x80000000u);
}
__device__ __forceinline__ float fdec(unsigned u) {
    return (u & 0x80000000u) ? __uint_as_float(u ^ 0x80000000u)
                             : __uint_as_float(~u);
}

// ---------------- tf32 mma.sync GEMM, warp tile 64x64, fused dual output ----
// C[M, Nt] = A[M, K=256] @ Bt^T, Bt is [Nt, K] row-major tf32-pre-rounded.
// Block 128x128, 128 threads (4 warps, 2x2), warp tile 64x64.
// Smem per stage 32KB: A frag-packed [8 mt][4 kt][32 lane][4],
//                      B pair-packed [8 ntp][4 kt][32 lane][4] (two frags/LDS.128).
// Output block goes to C1 if nBase < split else C2 (split % 128 == 0).
#define GM_SMEM 65536

__global__ __launch_bounds__(128, 2)
void gemm_mma(const float* __restrict__ A, const float* __restrict__ Bt,
              float* __restrict__ C1, float* __restrict__ C2,
              int M, int split, int ld1, int ld2) {
    extern __shared__ float sm[];
    const int K = 256;
    const int tid = threadIdx.x, lane = tid & 31, warp = tid >> 5;
    const int wm = warp >> 1, wn = warp & 1;
    const int mBase = blockIdx.y * 128;
    const int nBase = blockIdx.x * 128;
    float* Cp;
    int ld, cBase;
    if (nBase < split) { Cp = C1; ld = ld1; cBase = nBase; }
    else               { Cp = C2; ld = ld2; cBase = nBase - split; }

    float acc[4][8][4];
#pragma unroll
    for (int i = 0; i < 4; i++)
#pragma unroll
        for (int j = 0; j < 8; j++)
#pragma unroll
            for (int r = 0; r < 4; r++) acc[i][j][r] = 0.f;

    const int rowb = tid >> 3;          // 0..15, +16*l
    const int c4   = (tid & 7) * 4;
    const int kt   = c4 >> 3;
    const int hi   = (c4 >> 2) & 1;
    int dstA[8], dstB[8];
#pragma unroll
    for (int l = 0; l < 8; l++) {
        int row = rowb + 16 * l;
        int mt = row >> 4, rr = row & 15;
        dstA[l] = (mt * 4 + kt) * 128 + (rr & 7) * 16 + (rr >> 3) + hi * 2;
        int ntp = row >> 4, sub = (row >> 3) & 1, rn = row & 7;
        dstB[l] = (ntp * 4 + kt) * 128 + rn * 16 + sub * 2 + hi;
    }

    float4 aR[8], bR[8];
#pragma unroll
    for (int l = 0; l < 8; l++) {
        int gr = mBase + rowb + 16 * l;
        aR[l] = (gr < M) ? *reinterpret_cast<const float4*>(A + (size_t)gr * K + c4)
                         : make_float4(0.f, 0.f, 0.f, 0.f);
        bR[l] = *reinterpret_cast<const float4*>(Bt + (size_t)(nBase + rowb + 16 * l) * K + c4);
    }
    {
        float* As = sm;
        float* Bs = sm + 4096;
#pragma unroll
        for (int l = 0; l < 8; l++) {
            As[dstA[l]]      = to_tf32(aR[l].x);
            As[dstA[l] + 4]  = to_tf32(aR[l].y);
            As[dstA[l] + 8]  = to_tf32(aR[l].z);
            As[dstA[l] + 12] = to_tf32(aR[l].w);
            Bs[dstB[l]]      = bR[l].x;
            Bs[dstB[l] + 4]  = bR[l].y;
            Bs[dstB[l] + 8]  = bR[l].z;
            Bs[dstB[l] + 12] = bR[l].w;
        }
    }
    __syncthreads();

    int buf = 0;
    for (int k0 = 32; k0 <= K; k0 += 32) {
        const bool more = (k0 < K);
        if (more) {
#pragma unroll
            for (int l = 0; l < 8; l++) {
                int gr = mBase + rowb + 16 * l;
                aR[l] = (gr < M) ? *reinterpret_cast<const float4*>(A + (size_t)gr * K + k0 + c4)
                                 : make_float4(0.f, 0.f, 0.f, 0.f);
                bR[l] = *reinterpret_cast<const float4*>(Bt + (size_t)(nBase + rowb + 16 * l) * K + k0 + c4);
            }
        }
        {
            const float* As = sm + buf * 8192;
            const float* Bs = sm + buf * 8192 + 4096;
#pragma unroll
            for (int k = 0; k < 4; k++) {
                uint4 a[4];
#pragma unroll
                for (int i = 0; i < 4; i++)
                    a[i] = *reinterpret_cast<const uint4*>(As + ((wm * 4 + i) * 4 + k) * 128 + lane * 4);
#pragma unroll
                for (int p = 0; p < 4; p++) {
                    uint4 bb = *reinterpret_cast<const uint4*>(Bs + ((wn * 4 + p) * 4 + k) * 128 + lane * 4);
#pragma unroll
                    for (int i = 0; i < 4; i++) {
                        mma_tf32(acc[i][2 * p],     a[i], bb.x, bb.y);
                        mma_tf32(acc[i][2 * p + 1], a[i], bb.z, bb.w);
                    }
                }
            }
        }
        if (more) {
            float* As = sm + (buf ^ 1) * 8192;
            float* Bs = sm + (buf ^ 1) * 8192 + 4096;
#pragma unroll
            for (int l = 0; l < 8; l++) {
                As[dstA[l]]      = to_tf32(aR[l].x);
                As[dstA[l] + 4]  = to_tf32(aR[l].y);
                As[dstA[l] + 8]  = to_tf32(aR[l].z);
                As[dstA[l] + 12] = to_tf32(aR[l].w);
                Bs[dstB[l]]      = bR[l].x;
                Bs[dstB[l] + 4]  = bR[l].y;
                Bs[dstB[l] + 8]  = bR[l].z;
                Bs[dstB[l] + 12] = bR[l].w;
            }
            __syncthreads();
            buf ^= 1;
        }
    }

    // epilogue: direct float2 stores (C buffers padded to NPAD rows)
#pragma unroll
    for (int i = 0; i < 4; i++) {
        int r0 = mBase + wm * 64 + i * 16 + (lane >> 2);
#pragma unroll
        for (int j = 0; j < 8; j++) {
            int cc = cBase + wn * 64 + j * 8 + (lane & 3) * 2;
            *reinterpret_cast<float2*>(Cp + (size_t)r0 * ld + cc) =
                make_float2(acc[i][j][0], acc[i][j][1]);
            *reinterpret_cast<float2*>(Cp + (size_t)(r0 + 8) * ld + cc) =
                make_float2(acc[i][j][2], acc[i][j][3]);
        }
    }
}

// ---------------- weight transpose (+tf32 round) ----------------------------
__global__ void transpose_cvt(const float* __restrict__ W, float* __restrict__ Wt,
                              int K, int N) {
    __shared__ float t[32][33];
    int kb = blockIdx.y * 32, nb = blockIdx.x * 32;
    for (int i = threadIdx.y; i < 32; i += 8)
        t[i][threadIdx.x] = W[(size_t)(kb + i) * N + nb + threadIdx.x];
    __syncthreads();
    for (int i = threadIdx.y; i < 32; i += 8)
        Wt[(size_t)(nb + i) * K + kb + threadIdx.x] = to_tf32(t[threadIdx.x][i]);
}

// ---------------- CSR build --------------------------------------------------
__global__ void zero_int_kernel(int* __restrict__ p, int n) {
    int i = blockIdx.x * blockDim.x + threadIdx.x;
    if (i < n) p[i] = 0;
}
__global__ void count_deg_kernel(const int* __restrict__ dst, int* __restrict__ deg, int E) {
    int e = blockIdx.x * blockDim.x + threadIdx.x;
    if (e < E) atomicAdd(&deg[dst[e]], 1);
}
__global__ __launch_bounds__(1024)
void scan_kernel(const int* __restrict__ deg, int* __restrict__ rowptr, int n) {
    __shared__ int sums[1024];
    const int chunk = (n + 1023) / 1024;
    const int start = threadIdx.x * chunk;
    int s = 0;
    for (int i = 0; i < chunk; i++) {
        int idx = start + i;
        s += (idx < n) ? deg[idx] : 0;
    }
    sums[threadIdx.x] = s;
    __syncthreads();
    for (int off = 1; off < 1024; off <<= 1) {
        int v = 0;
        if (threadIdx.x >= off) v = sums[threadIdx.x - off];
        __syncthreads();
        if (threadIdx.x >= off) sums[threadIdx.x] += v;
        __syncthreads();
    }
    int base = (threadIdx.x == 0) ? 0 : sums[threadIdx.x - 1];
    for (int i = 0; i < chunk; i++) {
        int idx = start + i;
        if (idx < n) { rowptr[idx] = base; base += deg[idx]; }
    }
    if (threadIdx.x == 1023) rowptr[n] = sums[1023];
}
__global__ void copy_cursor_kernel(const int* __restrict__ rowptr, int* __restrict__ cursor, int n) {
    int i = blockIdx.x * blockDim.x + threadIdx.x;
    if (i < n) cursor[i] = rowptr[i];
}
__global__ void scatter_kernel(const int* __restrict__ dst, int* __restrict__ cursor,
                               int* __restrict__ eids, int E) {
    int e = blockIdx.x * blockDim.x + threadIdx.x;
    if (e < E) {
        int p = atomicAdd(&cursor[dst[e]], 1);
        eids[p] = e;
    }
}

// ---------------- edge / softmax / aggregation -------------------------------
__global__ void attn_kernel(const float* __restrict__ h,
                            const float* __restrict__ att_s,
                            const float* __restrict__ att_d,
                            float* __restrict__ asrc, float* __restrict__ adst,
                            int n, int C) {
    int warp = (blockIdx.x * blockDim.x + threadIdx.x) >> 5;
    int lane = threadIdx.x & 31;
    if (warp >= n) return;
    const float* hr = h + (size_t)warp * 4 * C;
#pragma unroll
    for (int hh = 0; hh < 4; hh++) {
        float s1 = 0.f, s2 = 0.f;
        for (int c = lane; c < C; c += 32) {
            float v = hr[hh * C + c];
            s1 += v * att_s[hh * C + c];
            s2 += v * att_d[hh * C + c];
        }
#pragma unroll
        for (int o = 16; o > 0; o >>= 1) {
            s1 += __shfl_down_sync(0xffffffffu, s1, o);
            s2 += __shfl_down_sync(0xffffffffu, s2, o);
        }
        if (lane == 0) { asrc[warp * 4 + hh] = s1; adst[warp * 4 + hh] = s2; }
    }
}

__global__ void init_md_kernel(unsigned* __restrict__ m, float* __restrict__ den, int n4) {
    int i = blockIdx.x * blockDim.x + threadIdx.x;
    if (i < n4) { m[i] = 0x007FFFFFu; den[i] = 0.f; }
}

// one thread per edge, all 4 heads vectorized
__global__ void edge_max_kernel(const int* __restrict__ src, const int* __restrict__ dst,
                                const float* __restrict__ asrc, const float* __restrict__ adst,
                                float* __restrict__ ebuf, unsigned* __restrict__ m, int E) {
    int e = blockIdx.x * blockDim.x + threadIdx.x;
    if (e >= E) return;
    int s = src[e], d = dst[e];
    float4 a = *reinterpret_cast<const float4*>(asrc + s * 4);
    float4 b = *reinterpret_cast<const float4*>(adst + d * 4);
    float4 v;
    v.x = a.x + b.x; v.x = v.x > 0.f ? v.x : 0.2f * v.x;
    v.y = a.y + b.y; v.y = v.y > 0.f ? v.y : 0.2f * v.y;
    v.z = a.z + b.z; v.z = v.z > 0.f ? v.z : 0.2f * v.z;
    v.w = a.w + b.w; v.w = v.w > 0.f ? v.w : 0.2f * v.w;
    *reinterpret_cast<float4*>(ebuf + e * 4) = v;
    atomicMax(&m[d * 4 + 0], fenc(v.x));
    atomicMax(&m[d * 4 + 1], fenc(v.y));
    atomicMax(&m[d * 4 + 2], fenc(v.z));
    atomicMax(&m[d * 4 + 3], fenc(v.w));
}

__global__ void edge_exp_kernel(const int* __restrict__ dst, const unsigned* __restrict__ m,
                                float* __restrict__ ebuf, float* __restrict__ den, int E) {
    int e = blockIdx.x * blockDim.x + threadIdx.x;
    if (e >= E) return;
    int d = dst[e];
    uint4 mu = *reinterpret_cast<const uint4*>(m + d * 4);
    float4 v = *reinterpret_cast<const float4*>(ebuf + e * 4);
    v.x = expf(v.x - fdec(mu.x));
    v.y = expf(v.y - fdec(mu.y));
    v.z = expf(v.z - fdec(mu.z));
    v.w = expf(v.w - fdec(mu.w));
    *reinterpret_cast<float4*>(ebuf + e * 4) = v;
    atomicAdd(&den[d * 4 + 0], v.x);
    atomicAdd(&den[d * 4 + 1], v.y);
    atomicAdd(&den[d * 4 + 2], v.z);
    atomicAdd(&den[d * 4 + 3], v.w);
}

// CSR pull: one warp per node, all heads together. HW = 4*C, R = HW/32.
template <int C>
__global__ __launch_bounds__(256)
void agg_pull_kernel(const int* __restrict__ rowptr, const int* __restrict__ eids,
                     const int* __restrict__ src, const float* __restrict__ h,
                     const float* __restrict__ ebuf, const float* __restrict__ den,
                     float* __restrict__ agg, int n) {
    const int node = blockIdx.x * 8 + (threadIdx.x >> 5);
    if (node >= n) return;
    const int lane = threadIdx.x & 31;
    const int HW = 4 * C;
    const int R = HW / 32;           // 8 (C=64) or 16 (C=128)
    const int JH = C / 32;           // regs per head
    const int beg = rowptr[node], end = rowptr[node + 1];

    float acc[R];
#pragma unroll
    for (int j = 0; j < R; j++) acc[j] = 0.f;

    for (int i = beg; i < end; i++) {
        int e = eids[i];
        int s = src[e];
        float4 w4 = *reinterpret_cast<const float4*>(ebuf + (size_t)e * 4);
        float w[4] = {w4.x, w4.y, w4.z, w4.w};
        const float* hs = h + (size_t)s * HW + lane;
#pragma unroll
        for (int j = 0; j < R; j++) acc[j] += w[j / JH] * hs[j * 32];
    }
    float4 d4 = *reinterpret_cast<const float4*>(den + (size_t)node * 4);
    float inv[4] = {1.f / (d4.x + 1e-16f), 1.f / (d4.y + 1e-16f),
                    1.f / (d4.z + 1e-16f), 1.f / (d4.w + 1e-16f)};
    float* out = agg + (size_t)node * HW + lane;
#pragma unroll
    for (int j = 0; j < R; j++) out[j * 32] = acc[j] * inv[j / JH];
}

__global__ void finalize_concat_kernel(const float* __restrict__ agg, const float* __restrict__ b,
                                       const float* __restrict__ lb, const float* __restrict__ lin,
                                       float* __restrict__ out, int total, int HW) {
    int idx = blockIdx.x * blockDim.x + threadIdx.x;
    if (idx >= total) return;
    int j = idx & (HW - 1);
    int row = idx / HW;
    float v = agg[idx] + b[j] + lin[(size_t)row * HW + j] + lb[j];
    out[idx] = v > 0.f ? v : expm1f(v);
}

__global__ void finalize_mean_kernel(const float* __restrict__ agg, const float* __restrict__ b,
                                     const float* __restrict__ lb, const float* __restrict__ lin,
                                     float* __restrict__ out, int n) {
    int idx = blockIdx.x * blockDim.x + threadIdx.x;
    if (idx >= n * 128) return;
    int ni = idx >> 7, j = idx & 127;
    const float* a = agg + (size_t)ni * 512;
    float v = 0.25f * (a[j] + a[128 + j] + a[256 + j] + a[384 + j])
              + b[j] + lin[(size_t)ni * 128 + j] + lb[j];
    out[idx] = v;
}

// ---------------- host side --------------------------------------------------
static void run_layer_rest(const float* hbuf, const float* as, const float* ad,
                           const float* b, const float* lb, const float* linbuf,
                           int HW, int C, float* outbuf, bool last,
                           const int* src, const int* dst,
                           float* aggbuf, float* asrcb, float* adstb,
                           unsigned* mb, float* denb, float* eb,
                           const int* rowptr, const int* eids, int n, int E) {
    attn_kernel<<<(n + 7) / 8, 256>>>(hbuf, as, ad, asrcb, adstb, n, C);
    init_md_kernel<<<(n * 4 + 255) / 256, 256>>>(mb, denb, n * 4);
    edge_max_kernel<<<(E + 255) / 256, 256>>>(src, dst, asrcb, adstb, eb, mb, E);
    edge_exp_kernel<<<(E + 255) / 256, 256>>>(dst, mb, eb, denb, E);
    int nblocks = (n + 7) / 8;
    if (C == 64)
        agg_pull_kernel<64><<<nblocks, 256>>>(rowptr, eids, src, hbuf, eb, denb, aggbuf, n);
    else
        agg_pull_kernel<128><<<nblocks, 256>>>(rowptr, eids, src, hbuf, eb, denb, aggbuf, n);
    if (!last)
        finalize_concat_kernel<<<(n * HW + 255) / 256, 256>>>(aggbuf, b, lb, linbuf, outbuf, n * HW, HW);
    else
        finalize_mean_kernel<<<(n * 128 + 255) / 256, 256>>>(aggbuf, b, lb, linbuf, outbuf, n);
}

extern "C" void kernel_launch(void* const* d_in, const int* in_sizes, int n_in,
                              void* d_out, int out_size) {
    const float* x  = (const float*)d_in[0];
    const int*   ei = (const int*)d_in[1];
    const int n = in_sizes[0] / 256;   // 50000
    const int E = in_sizes[1] / 2;     // 300000
    const int* src = ei;
    const int* dst = ei + E;

    cudaFuncSetAttribute(gemm_mma, cudaFuncAttributeMaxDynamicSharedMemorySize, GM_SMEM);

    float *hbuf, *linbuf, *aggbuf, *b0buf, *b1buf, *asrcb, *adstb, *denb, *eb, *wt;
    unsigned* mb;
    int *deg, *rowptr, *cursor, *eids;
    cudaGetSymbolAddress((void**)&hbuf, g_h);
    cudaGetSymbolAddress((void**)&linbuf, g_lin);
    cudaGetSymbolAddress((void**)&aggbuf, g_agg);
    cudaGetSymbolAddress((void**)&b0buf, g_buf0);
    cudaGetSymbolAddress((void**)&b1buf, g_buf1);
    cudaGetSymbolAddress((void**)&asrcb, g_asrc);
    cudaGetSymbolAddress((void**)&adstb, g_adst);
    cudaGetSymbolAddress((void**)&mb, g_m);
    cudaGetSymbolAddress((void**)&denb, g_den);
    cudaGetSymbolAddress((void**)&eb, g_e);
    cudaGetSymbolAddress((void**)&deg, g_deg);
    cudaGetSymbolAddress((void**)&rowptr, g_rowptr);
    cudaGetSymbolAddress((void**)&cursor, g_cursor);
    cudaGetSymbolAddress((void**)&eids, g_eids);
    cudaGetSymbolAddress((void**)&wt, g_wt);

    // fused weight regions: [gat W ; linear W] stacked in N (rows of Bt)
    float* wt0  = wt;             // 256 + 256 rows (K=256)
    float* lwt0 = wt + 65536;
    float* wt1  = wt + 131072;
    float* lwt1 = wt + 196608;
    float* wt2  = wt + 262144;    // 512 rows
    float* lwt2 = wt + 393216;    // 128 rows

    const int gy = (n + 127) / 128;   // 391
    dim3 tb(32, 8);

    // ordered so the 4th launch (the ncu capture slot) is the big fused GEMM
    transpose_cvt<<<dim3(8, 8), tb>>>((const float*)d_in[2], wt0, 256, 256);
    transpose_cvt<<<dim3(8, 8), tb>>>((const float*)d_in[6], lwt0, 256, 256);
    zero_int_kernel<<<(n + 255) / 256, 256>>>(deg, n);
    gemm_mma<<<dim3(4, gy), 128, GM_SMEM>>>(x, wt0, hbuf, linbuf, n, 256, 256, 256); // 4th
    count_deg_kernel<<<(E + 255) / 256, 256>>>(dst, deg, E);
    scan_kernel<<<1, 1024>>>(deg, rowptr, n);
    copy_cursor_kernel<<<(n + 255) / 256, 256>>>(rowptr, cursor, n);
    scatter_kernel<<<(E + 255) / 256, 256>>>(dst, cursor, eids, E);
    transpose_cvt<<<dim3(8, 8), tb>>>((const float*)d_in[8], wt1, 256, 256);
    transpose_cvt<<<dim3(8, 8), tb>>>((const float*)d_in[12], lwt1, 256, 256);
    transpose_cvt<<<dim3(16, 8), tb>>>((const float*)d_in[14], wt2, 256, 512);
    transpose_cvt<<<dim3(4, 8), tb>>>((const float*)d_in[18], lwt2, 256, 128);

    // layer 0
    run_layer_rest(hbuf, (const float*)d_in[3], (const float*)d_in[4],
                   (const float*)d_in[5], (const float*)d_in[7], linbuf,
                   256, 64, b0buf, false, src, dst, aggbuf, asrcb, adstb,
                   mb, denb, eb, rowptr, eids, n, E);
    // layer 1
    gemm_mma<<<dim3(4, gy), 128, GM_SMEM>>>(b0buf, wt1, hbuf, linbuf, n, 256, 256, 256);
    run_layer_rest(hbuf, (const float*)d_in[9], (const float*)d_in[10],
                   (const float*)d_in[11], (const float*)d_in[13], linbuf,
                   256, 64, b1buf, false, src, dst, aggbuf, asrcb, adstb,
                   mb, denb, eb, rowptr, eids, n, E);
    // layer 2 (fused N = 512 + 128 = 640)
    gemm_mma<<<dim3(5, gy), 128, GM_SMEM>>>(b1buf, wt2, hbuf, linbuf, n, 512, 512, 128);
    run_layer_rest(hbuf, (const float*)d_in[15], (const float*)d_in[16],
                   (const float*)d_in[17], (const float*)d_in[19], linbuf,
                   512, 128, (float*)d_out, true, src, dst, aggbuf, asrcb, adstb,
                   mb, denb, eb, rowptr, eids, n, E);
}

// round 7
// speedup vs baseline: 3.6322x; 1.2977x over previous
#include <cuda_runtime.h>
#include <math.h>
#include <cstdint>

#define NN 50000
#define NE 300000
#define NPAD (NN + 128)

// ---------------- scratch (device globals; no runtime allocation) ----------
__device__ float    g_h   [(size_t)NPAD * 512];
__device__ float    g_lin [(size_t)NPAD * 256];
__device__ float    g_agg [(size_t)NN * 512];
__device__ float    g_buf0[(size_t)NN * 256];
__device__ float    g_buf1[(size_t)NN * 256];
__device__ float    g_asrc[NN * 4];
__device__ float    g_adst[NN * 4];
__device__ unsigned g_m   [NN * 4];
__device__ float    g_den [NN * 4];
__device__ float    g_e   [NE * 4];
__device__ int      g_deg [NN];
__device__ int      g_rowptr[NN + 1];
__device__ int      g_cursor[NN];
__device__ int      g_eids[NE];
__device__ float    g_wt  [425984];   // transposed (tf32-rounded) weights

// ---------------- helpers ---------------------------------------------------
__device__ __forceinline__ float to_tf32(float f) {
    float o;
    asm("cvt.rna.tf32.f32 %0, %1;" : "=f"(o) : "f"(f));
    return o;
}
__device__ __forceinline__ uint32_t smem_u32(const void* p) {
    uint32_t a;
    asm("{ .reg .u64 t; cvta.to.shared.u64 t, %1; cvt.u32.u64 %0, t; }" : "=r"(a) : "l"(p));
    return a;
}
__device__ __forceinline__ void ldsm_x4(uint32_t& r0, uint32_t& r1, uint32_t& r2,
                                        uint32_t& r3, uint32_t addr) {
    asm volatile("ldmatrix.sync.aligned.m8n8.x4.shared.b16 {%0,%1,%2,%3}, [%4];"
                 : "=r"(r0), "=r"(r1), "=r"(r2), "=r"(r3) : "r"(addr));
}
__device__ __forceinline__ void mma_tf32(float* c, uint32_t a0, uint32_t a1,
                                         uint32_t a2, uint32_t a3,
                                         uint32_t b0, uint32_t b1) {
    asm volatile(
        "mma.sync.aligned.m16n8k8.row.col.f32.tf32.tf32.f32 "
        "{%0,%1,%2,%3}, {%4,%5,%6,%7}, {%8,%9}, {%0,%1,%2,%3};"
        : "+f"(c[0]), "+f"(c[1]), "+f"(c[2]), "+f"(c[3])
        : "r"(a0), "r"(a1), "r"(a2), "r"(a3), "r"(b0), "r"(b1));
}
__device__ __forceinline__ unsigned fenc(float f) {
    unsigned u = __float_as_uint(f);
    return (u & 0x80000000u) ? ~u : (u | 0x80000000u);
}
__device__ __forceinline__ float fdec(unsigned u) {
    return (u & 0x80000000u) ? __uint_as_float(u ^ 0x80000000u)
                             : __uint_as_float(~u);
}

// ---------------- tf32 mma.sync GEMM: swizzled smem + ldmatrix --------------
// C[M, Nt] = A[M, K=256] @ Bt^T, Bt is [Nt, K] row-major tf32-pre-rounded.
// Block 128x128, 128 threads (4 warps 2x2), warp tile 64x64.
// Smem: per-stage A tile 128x32 f32 (128B rows, SW128 swizzle), B tile same.
// Stores are STS.128; fragment loads are ldmatrix.x4 (b16 bit-movement).
// Output block -> C1 if nBase < split else C2 (split % 128 == 0).
#define GM_SMEM 65536

__global__ __launch_bounds__(128, 2)
void gemm_mma(const float* __restrict__ A, const float* __restrict__ Bt,
              float* __restrict__ C1, float* __restrict__ C2,
              int M, int split, int ld1, int ld2) {
    extern __shared__ float sm[];
    const int K = 256;
    const int tid = threadIdx.x, lane = tid & 31, warp = tid >> 5;
    const int wm = warp >> 1, wn = warp & 1;
    const int mBase = blockIdx.y * 128;
    const int nBase = blockIdx.x * 128;
    float* Cp;
    int ld, cBase;
    if (nBase < split) { Cp = C1; ld = ld1; cBase = nBase; }
    else               { Cp = C2; ld = ld2; cBase = nBase - split; }

    const uint32_t sbase = smem_u32(sm);

    float acc[4][8][4];
#pragma unroll
    for (int i = 0; i < 4; i++)
#pragma unroll
        for (int j = 0; j < 8; j++)
#pragma unroll
            for (int r = 0; r < 4; r++) acc[i][j][r] = 0.f;

    // ---- global load / smem store indexing ----
    const int rowb = tid >> 3;           // 0..15, +16*l
    const int c4   = (tid & 7) * 4;      // k offset of this thread's float4
    const int unit = tid & 7;            // 16B unit within the 128B row
    const int rl3  = rowb & 7;
    int dstS[8];                          // float offsets (same for A and B regions)
#pragma unroll
    for (int l = 0; l < 8; l++) {
        int row = rowb + 16 * l;
        dstS[l] = row * 32 + ((unit ^ rl3) << 2);
    }

    // ---- ldmatrix lane constants ----
    const int g  = lane >> 3, iL = lane & 7;
    const int rA  = wm * 64 + iL + (g & 1) * 8;   // + mt*16
    const int kA  = g >> 1;                        // k-half selector
    const int rB  = wn * 64 + iL + (g >> 1) * 8;  // + np*16
    const int kB  = g & 1;
    const int rA7 = rA & 7, rB7 = rB & 7;

    float4 aR[8], bR[8];
#pragma unroll
    for (int l = 0; l < 8; l++) {
        int gr = mBase + rowb + 16 * l;
        aR[l] = (gr < M) ? *reinterpret_cast<const float4*>(A + (size_t)gr * K + c4)
                         : make_float4(0.f, 0.f, 0.f, 0.f);
        bR[l] = *reinterpret_cast<const float4*>(Bt + (size_t)(nBase + rowb + 16 * l) * K + c4);
    }
    {
        float* As = sm;            // stage 0: A at 0, B at +4096 floats
        float* Bs = sm + 4096;
#pragma unroll
        for (int l = 0; l < 8; l++) {
            float4 av = make_float4(to_tf32(aR[l].x), to_tf32(aR[l].y),
                                    to_tf32(aR[l].z), to_tf32(aR[l].w));
            *reinterpret_cast<float4*>(As + dstS[l]) = av;
            *reinterpret_cast<float4*>(Bs + dstS[l]) = bR[l];
        }
    }
    __syncthreads();

    int buf = 0;
    for (int k0 = 32; k0 <= K; k0 += 32) {
        const bool more = (k0 < K);
        if (more) {
#pragma unroll
            for (int l = 0; l < 8; l++) {
                int gr = mBase + rowb + 16 * l;
                aR[l] = (gr < M) ? *reinterpret_cast<const float4*>(A + (size_t)gr * K + k0 + c4)
                                 : make_float4(0.f, 0.f, 0.f, 0.f);
                bR[l] = *reinterpret_cast<const float4*>(Bt + (size_t)(nBase + rowb + 16 * l) * K + k0 + c4);
            }
        }
        // ---- compute current stage ----
        {
            const uint32_t aB = sbase + buf * 32768u;          // bytes
            const uint32_t bB = aB + 16384u;
#pragma unroll
            for (int kt = 0; kt < 4; kt++) {
                uint32_t a[4][4];
#pragma unroll
                for (int mt = 0; mt < 4; mt++) {
                    uint32_t addr = aB + (uint32_t)(rA + mt * 16) * 128u +
                                    (uint32_t)(((kt * 2 + kA) ^ rA7) << 4);
                    ldsm_x4(a[mt][0], a[mt][1], a[mt][2], a[mt][3], addr);
                }
#pragma unroll
                for (int np = 0; np < 4; np++) {
                    uint32_t b0, b1, b2, b3;
                    uint32_t addr = bB + (uint32_t)(rB + np * 16) * 128u +
                                    (uint32_t)(((kt * 2 + kB) ^ rB7) << 4);
                    ldsm_x4(b0, b1, b2, b3, addr);
#pragma unroll
                    for (int i = 0; i < 4; i++) {
                        mma_tf32(acc[i][2 * np],     a[i][0], a[i][1], a[i][2], a[i][3], b0, b1);
                        mma_tf32(acc[i][2 * np + 1], a[i][0], a[i][1], a[i][2], a[i][3], b2, b3);
                    }
                }
            }
        }
        if (more) {
            float* As = sm + (buf ^ 1) * 8192;
            float* Bs = As + 4096;
#pragma unroll
            for (int l = 0; l < 8; l++) {
                float4 av = make_float4(to_tf32(aR[l].x), to_tf32(aR[l].y),
                                        to_tf32(aR[l].z), to_tf32(aR[l].w));
                *reinterpret_cast<float4*>(As + dstS[l]) = av;
                *reinterpret_cast<float4*>(Bs + dstS[l]) = bR[l];
            }
            __syncthreads();
            buf ^= 1;
        }
    }

    // epilogue: direct float2 stores (C buffers padded to NPAD rows)
#pragma unroll
    for (int i = 0; i < 4; i++) {
        int r0 = mBase + wm * 64 + i * 16 + (lane >> 2);
#pragma unroll
        for (int j = 0; j < 8; j++) {
            int cc = cBase + wn * 64 + j * 8 + (lane & 3) * 2;
            *reinterpret_cast<float2*>(Cp + (size_t)r0 * ld + cc) =
                make_float2(acc[i][j][0], acc[i][j][1]);
            *reinterpret_cast<float2*>(Cp + (size_t)(r0 + 8) * ld + cc) =
                make_float2(acc[i][j][2], acc[i][j][3]);
        }
    }
}

// ---------------- weight transpose (+tf32 round) ----------------------------
__global__ void transpose_cvt(const float* __restrict__ W, float* __restrict__ Wt,
                              int K, int N) {
    __shared__ float t[32][33];
    int kb = blockIdx.y * 32, nb = blockIdx.x * 32;
    for (int i = threadIdx.y; i < 32; i += 8)
        t[i][threadIdx.x] = W[(size_t)(kb + i) * N + nb + threadIdx.x];
    __syncthreads();
    for (int i = threadIdx.y; i < 32; i += 8)
        Wt[(size_t)(nb + i) * K + kb + threadIdx.x] = to_tf32(t[threadIdx.x][i]);
}

// ---------------- CSR build --------------------------------------------------
__global__ void zero_int_kernel(int* __restrict__ p, int n) {
    int i = blockIdx.x * blockDim.x + threadIdx.x;
    if (i < n) p[i] = 0;
}
__global__ void count_deg_kernel(const int* __restrict__ dst, int* __restrict__ deg, int E) {
    int e = blockIdx.x * blockDim.x + threadIdx.x;
    if (e < E) atomicAdd(&deg[dst[e]], 1);
}
__global__ __launch_bounds__(1024)
void scan_kernel(const int* __restrict__ deg, int* __restrict__ rowptr, int n) {
    __shared__ int sums[1024];
    const int chunk = (n + 1023) / 1024;
    const int start = threadIdx.x * chunk;
    int s = 0;
    for (int i = 0; i < chunk; i++) {
        int idx = start + i;
        s += (idx < n) ? deg[idx] : 0;
    }
    sums[threadIdx.x] = s;
    __syncthreads();
    for (int off = 1; off < 1024; off <<= 1) {
        int v = 0;
        if (threadIdx.x >= off) v = sums[threadIdx.x - off];
        __syncthreads();
        if (threadIdx.x >= off) sums[threadIdx.x] += v;
        __syncthreads();
    }
    int base = (threadIdx.x == 0) ? 0 : sums[threadIdx.x - 1];
    for (int i = 0; i < chunk; i++) {
        int idx = start + i;
        if (idx < n) { rowptr[idx] = base; base += deg[idx]; }
    }
    if (threadIdx.x == 1023) rowptr[n] = sums[1023];
}
__global__ void copy_cursor_kernel(const int* __restrict__ rowptr, int* __restrict__ cursor, int n) {
    int i = blockIdx.x * blockDim.x + threadIdx.x;
    if (i < n) cursor[i] = rowptr[i];
}
__global__ void scatter_kernel(const int* __restrict__ dst, int* __restrict__ cursor,
                               int* __restrict__ eids, int E) {
    int e = blockIdx.x * blockDim.x + threadIdx.x;
    if (e < E) {
        int p = atomicAdd(&cursor[dst[e]], 1);
        eids[p] = e;
    }
}

// ---------------- edge / softmax / aggregation -------------------------------
__global__ void attn_kernel(const float* __restrict__ h,
                            const float* __restrict__ att_s,
                            const float* __restrict__ att_d,
                            float* __restrict__ asrc, float* __restrict__ adst,
                            int n, int C) {
    int warp = (blockIdx.x * blockDim.x + threadIdx.x) >> 5;
    int lane = threadIdx.x & 31;
    if (warp >= n) return;
    const float* hr = h + (size_t)warp * 4 * C;
#pragma unroll
    for (int hh = 0; hh < 4; hh++) {
        float s1 = 0.f, s2 = 0.f;
        for (int c = lane; c < C; c += 32) {
            float v = hr[hh * C + c];
            s1 += v * att_s[hh * C + c];
            s2 += v * att_d[hh * C + c];
        }
#pragma unroll
        for (int o = 16; o > 0; o >>= 1) {
            s1 += __shfl_down_sync(0xffffffffu, s1, o);
            s2 += __shfl_down_sync(0xffffffffu, s2, o);
        }
        if (lane == 0) { asrc[warp * 4 + hh] = s1; adst[warp * 4 + hh] = s2; }
    }
}

__global__ void init_md_kernel(unsigned* __restrict__ m, float* __restrict__ den, int n4) {
    int i = blockIdx.x * blockDim.x + threadIdx.x;
    if (i < n4) { m[i] = 0x007FFFFFu; den[i] = 0.f; }
}

__global__ void edge_max_kernel(const int* __restrict__ src, const int* __restrict__ dst,
                                const float* __restrict__ asrc, const float* __restrict__ adst,
                                float* __restrict__ ebuf, unsigned* __restrict__ m, int E) {
    int e = blockIdx.x * blockDim.x + threadIdx.x;
    if (e >= E) return;
    int s = src[e], d = dst[e];
    float4 a = *reinterpret_cast<const float4*>(asrc + s * 4);
    float4 b = *reinterpret_cast<const float4*>(adst + d * 4);
    float4 v;
    v.x = a.x + b.x; v.x = v.x > 0.f ? v.x : 0.2f * v.x;
    v.y = a.y + b.y; v.y = v.y > 0.f ? v.y : 0.2f * v.y;
    v.z = a.z + b.z; v.z = v.z > 0.f ? v.z : 0.2f * v.z;
    v.w = a.w + b.w; v.w = v.w > 0.f ? v.w : 0.2f * v.w;
    *reinterpret_cast<float4*>(ebuf + e * 4) = v;
    atomicMax(&m[d * 4 + 0], fenc(v.x));
    atomicMax(&m[d * 4 + 1], fenc(v.y));
    atomicMax(&m[d * 4 + 2], fenc(v.z));
    atomicMax(&m[d * 4 + 3], fenc(v.w));
}

__global__ void edge_exp_kernel(const int* __restrict__ dst, const unsigned* __restrict__ m,
                                float* __restrict__ ebuf, float* __restrict__ den, int E) {
    int e = blockIdx.x * blockDim.x + threadIdx.x;
    if (e >= E) return;
    int d = dst[e];
    uint4 mu = *reinterpret_cast<const uint4*>(m + d * 4);
    float4 v = *reinterpret_cast<const float4*>(ebuf + e * 4);
    v.x = expf(v.x - fdec(mu.x));
    v.y = expf(v.y - fdec(mu.y));
    v.z = expf(v.z - fdec(mu.z));
    v.w = expf(v.w - fdec(mu.w));
    *reinterpret_cast<float4*>(ebuf + e * 4) = v;
    atomicAdd(&den[d * 4 + 0], v.x);
    atomicAdd(&den[d * 4 + 1], v.y);
    atomicAdd(&den[d * 4 + 2], v.z);
    atomicAdd(&den[d * 4 + 3], v.w);
}

template <int C>
__global__ __launch_bounds__(256)
void agg_pull_kernel(const int* __restrict__ rowptr, const int* __restrict__ eids,
                     const int* __restrict__ src, const float* __restrict__ h,
                     const float* __restrict__ ebuf, const float* __restrict__ den,
                     float* __restrict__ agg, int n) {
    const int node = blockIdx.x * 8 + (threadIdx.x >> 5);
    if (node >= n) return;
    const int lane = threadIdx.x & 31;
    const int HW = 4 * C;
    const int R = HW / 32;
    const int JH = C / 32;
    const int beg = rowptr[node], end = rowptr[node + 1];

    float acc[R];
#pragma unroll
    for (int j = 0; j < R; j++) acc[j] = 0.f;

    for (int i = beg; i < end; i++) {
        int e = eids[i];
        int s = src[e];
        float4 w4 = *reinterpret_cast<const float4*>(ebuf + (size_t)e * 4);
        float w[4] = {w4.x, w4.y, w4.z, w4.w};
        const float* hs = h + (size_t)s * HW + lane;
#pragma unroll
        for (int j = 0; j < R; j++) acc[j] += w[j / JH] * hs[j * 32];
    }
    float4 d4 = *reinterpret_cast<const float4*>(den + (size_t)node * 4);
    float inv[4] = {1.f / (d4.x + 1e-16f), 1.f / (d4.y + 1e-16f),
                    1.f / (d4.z + 1e-16f), 1.f / (d4.w + 1e-16f)};
    float* out = agg + (size_t)node * HW + lane;
#pragma unroll
    for (int j = 0; j < R; j++) out[j * 32] = acc[j] * inv[j / JH];
}

__global__ void finalize_concat_kernel(const float* __restrict__ agg, const float* __restrict__ b,
                                       const float* __restrict__ lb, const float* __restrict__ lin,
                                       float* __restrict__ out, int total, int HW) {
    int idx = blockIdx.x * blockDim.x + threadIdx.x;
    if (idx >= total) return;
    int j = idx & (HW - 1);
    int row = idx / HW;
    float v = agg[idx] + b[j] + lin[(size_t)row * HW + j] + lb[j];
    out[idx] = v > 0.f ? v : expm1f(v);
}

__global__ void finalize_mean_kernel(const float* __restrict__ agg, const float* __restrict__ b,
                                     const float* __restrict__ lb, const float* __restrict__ lin,
                                     float* __restrict__ out, int n) {
    int idx = blockIdx.x * blockDim.x + threadIdx.x;
    if (idx >= n * 128) return;
    int ni = idx >> 7, j = idx & 127;
    const float* a = agg + (size_t)ni * 512;
    float v = 0.25f * (a[j] + a[128 + j] + a[256 + j] + a[384 + j])
              + b[j] + lin[(size_t)ni * 128 + j] + lb[j];
    out[idx] = v;
}

// ---------------- host side --------------------------------------------------
static void run_layer_rest(const float* hbuf, const float* as, const float* ad,
                           const float* b, const float* lb, const float* linbuf,
                           int HW, int C, float* outbuf, bool last,
                           const int* src, const int* dst,
                           float* aggbuf, float* asrcb, float* adstb,
                           unsigned* mb, float* denb, float* eb,
                           const int* rowptr, const int* eids, int n, int E) {
    attn_kernel<<<(n + 7) / 8, 256>>>(hbuf, as, ad, asrcb, adstb, n, C);
    init_md_kernel<<<(n * 4 + 255) / 256, 256>>>(mb, denb, n * 4);
    edge_max_kernel<<<(E + 255) / 256, 256>>>(src, dst, asrcb, adstb, eb, mb, E);
    edge_exp_kernel<<<(E + 255) / 256, 256>>>(dst, mb, eb, denb, E);
    int nblocks = (n + 7) / 8;
    if (C == 64)
        agg_pull_kernel<64><<<nblocks, 256>>>(rowptr, eids, src, hbuf, eb, denb, aggbuf, n);
    else
        agg_pull_kernel<128><<<nblocks, 256>>>(rowptr, eids, src, hbuf, eb, denb, aggbuf, n);
    if (!last)
        finalize_concat_kernel<<<(n * HW + 255) / 256, 256>>>(aggbuf, b, lb, linbuf, outbuf, n * HW, HW);
    else
        finalize_mean_kernel<<<(n * 128 + 255) / 256, 256>>>(aggbuf, b, lb, linbuf, outbuf, n);
}

extern "C" void kernel_launch(void* const* d_in, const int* in_sizes, int n_in,
                              void* d_out, int out_size) {
    const float* x  = (const float*)d_in[0];
    const int*   ei = (const int*)d_in[1];
    const int n = in_sizes[0] / 256;   // 50000
    const int E = in_sizes[1] / 2;     // 300000
    const int* src = ei;
    const int* dst = ei + E;

    cudaFuncSetAttribute(gemm_mma, cudaFuncAttributeMaxDynamicSharedMemorySize, GM_SMEM);

    float *hbuf, *linbuf, *aggbuf, *b0buf, *b1buf, *asrcb, *adstb, *denb, *eb, *wt;
    unsigned* mb;
    int *deg, *rowptr, *cursor, *eids;
    cudaGetSymbolAddress((void**)&hbuf, g_h);
    cudaGetSymbolAddress((void**)&linbuf, g_lin);
    cudaGetSymbolAddress((void**)&aggbuf, g_agg);
    cudaGetSymbolAddress((void**)&b0buf, g_buf0);
    cudaGetSymbolAddress((void**)&b1buf, g_buf1);
    cudaGetSymbolAddress((void**)&asrcb, g_asrc);
    cudaGetSymbolAddress((void**)&adstb, g_adst);
    cudaGetSymbolAddress((void**)&mb, g_m);
    cudaGetSymbolAddress((void**)&denb, g_den);
    cudaGetSymbolAddress((void**)&eb, g_e);
    cudaGetSymbolAddress((void**)&deg, g_deg);
    cudaGetSymbolAddress((void**)&rowptr, g_rowptr);
    cudaGetSymbolAddress((void**)&cursor, g_cursor);
    cudaGetSymbolAddress((void**)&eids, g_eids);
    cudaGetSymbolAddress((void**)&wt, g_wt);

    // fused weight regions: [gat W ; linear W] stacked in N (rows of Bt)
    float* wt0  = wt;             // 256 + 256 rows (K=256)
    float* lwt0 = wt + 65536;
    float* wt1  = wt + 131072;
    float* lwt1 = wt + 196608;
    float* wt2  = wt + 262144;    // 512 rows
    float* lwt2 = wt + 393216;    // 128 rows

    const int gy = (n + 127) / 128;   // 391
    dim3 tb(32, 8);

    // ordered so the 4th launch (the ncu capture slot) is the big fused GEMM
    transpose_cvt<<<dim3(8, 8), tb>>>((const float*)d_in[2], wt0, 256, 256);
    transpose_cvt<<<dim3(8, 8), tb>>>((const float*)d_in[6], lwt0, 256, 256);
    zero_int_kernel<<<(n + 255) / 256, 256>>>(deg, n);
    gemm_mma<<<dim3(4, gy), 128, GM_SMEM>>>(x, wt0, hbuf, linbuf, n, 256, 256, 256); // 4th
    count_deg_kernel<<<(E + 255) / 256, 256>>>(dst, deg, E);
    scan_kernel<<<1, 1024>>>(deg, rowptr, n);
    copy_cursor_kernel<<<(n + 255) / 256, 256>>>(rowptr, cursor, n);
    scatter_kernel<<<(E + 255) / 256, 256>>>(dst, cursor, eids, E);
    transpose_cvt<<<dim3(8, 8), tb>>>((const float*)d_in[8], wt1, 256, 256);
    transpose_cvt<<<dim3(8, 8), tb>>>((const float*)d_in[12], lwt1, 256, 256);
    transpose_cvt<<<dim3(16, 8), tb>>>((const float*)d_in[14], wt2, 256, 512);
    transpose_cvt<<<dim3(4, 8), tb>>>((const float*)d_in[18], lwt2, 256, 128);

    // layer 0
    run_layer_rest(hbuf, (const float*)d_in[3], (const float*)d_in[4],
                   (const float*)d_in[5], (const float*)d_in[7], linbuf,
                   256, 64, b0buf, false, src, dst, aggbuf, asrcb, adstb,
                   mb, denb, eb, rowptr, eids, n, E);
    // layer 1
    gemm_mma<<<dim3(4, gy), 128, GM_SMEM>>>(b0buf, wt1, hbuf, linbuf, n, 256, 256, 256);
    run_layer_rest(hbuf, (const float*)d_in[9], (const float*)d_in[10],
                   (const float*)d_in[11], (const float*)d_in[13], linbuf,
                   256, 64, b1buf, false, src, dst, aggbuf, asrcb, adstb,
                   mb, denb, eb, rowptr, eids, n, E);
    // layer 2 (fused N = 512 + 128 = 640)
    gemm_mma<<<dim3(5, gy), 128, GM_SMEM>>>(b1buf, wt2, hbuf, linbuf, n, 512, 512, 128);
    run_layer_rest(hbuf, (const float*)d_in[15], (const float*)d_in[16],
                   (const float*)d_in[17], (const float*)d_in[19], linbuf,
                   512, 128, (float*)d_out, true, src, dst, aggbuf, asrcb, adstb,
                   mb, denb, eb, rowptr, eids, n, E);
}

// round 9
// speedup vs baseline: 4.0347x; 1.1108x over previous
#include <cuda_runtime.h>
#include <math.h>
#include <cstdint>

#define NN 50000
#define NE 300000
#define NPAD (NN + 128)

// ---------------- scratch (device globals; no runtime allocation) ----------
__device__ float    g_h   [(size_t)NPAD * 512];
__device__ float    g_lin [(size_t)NPAD * 256];
__device__ float    g_buf0[(size_t)NN * 256];
__device__ float    g_buf1[(size_t)NN * 256];
__device__ float    g_asrc[NN * 4];
__device__ float    g_adst[NN * 4];
__device__ unsigned g_m   [NN * 4];
__device__ float    g_den [NN * 4];
__device__ float    g_e   [NE * 4];
__device__ int      g_deg [NN];
__device__ int      g_rowptr[NN + 1];
__device__ int      g_cursor[NN];
__device__ int      g_eids[NE];
__device__ float    g_wt  [425984];   // transposed (tf32-rounded) weights

// ---------------- helpers ---------------------------------------------------
__device__ __forceinline__ float to_tf32(float f) {
    float o;
    asm("cvt.rna.tf32.f32 %0, %1;" : "=f"(o) : "f"(f));
    return o;
}
__device__ __forceinline__ uint32_t smem_u32(const void* p) {
    uint32_t a;
    asm("{ .reg .u64 t; cvta.to.shared.u64 t, %1; cvt.u32.u64 %0, t; }" : "=r"(a) : "l"(p));
    return a;
}
__device__ __forceinline__ void ldsm_x4(uint32_t& r0, uint32_t& r1, uint32_t& r2,
                                        uint32_t& r3, uint32_t addr) {
    asm volatile("ldmatrix.sync.aligned.m8n8.x4.shared.b16 {%0,%1,%2,%3}, [%4];"
                 : "=r"(r0), "=r"(r1), "=r"(r2), "=r"(r3) : "r"(addr));
}
__device__ __forceinline__ void mma_tf32(float* c, uint32_t a0, uint32_t a1,
                                         uint32_t a2, uint32_t a3,
                                         uint32_t b0, uint32_t b1) {
    asm volatile(
        "mma.sync.aligned.m16n8k8.row.col.f32.tf32.tf32.f32 "
        "{%0,%1,%2,%3}, {%4,%5,%6,%7}, {%8,%9}, {%0,%1,%2,%3};"
        : "+f"(c[0]), "+f"(c[1]), "+f"(c[2]), "+f"(c[3])
        : "r"(a0), "r"(a1), "r"(a2), "r"(a3), "r"(b0), "r"(b1));
}
__device__ __forceinline__ unsigned fenc(float f) {
    unsigned u = __float_as_uint(f);
    return (u & 0x80000000u) ? ~u : (u | 0x80000000u);
}
__device__ __forceinline__ float fdec(unsigned u) {
    return (u & 0x80000000u) ? __uint_as_float(u ^ 0x80000000u)
                             : __uint_as_float(~u);
}

// ---------------- tf32 mma.sync GEMM: swizzled smem + ldmatrix (round-7) ----
// C[M, Nt] = A[M, K=256] @ Bt^T, Bt is [Nt, K] row-major tf32-pre-rounded.
// Block 128x128, 128 threads (4 warps 2x2), warp tile 64x64.
// Smem: per-stage A tile 128x32 f32 (128B rows, SW128 swizzle), B tile same.
// Output block -> C1 if nBase < split else C2 (split % 128 == 0).
#define GM_SMEM 65536

__global__ __launch_bounds__(128, 2)
void gemm_mma(const float* __restrict__ A, const float* __restrict__ Bt,
              float* __restrict__ C1, float* __restrict__ C2,
              int M, int split, int ld1, int ld2) {
    extern __shared__ float sm[];
    const int K = 256;
    const int tid = threadIdx.x, lane = tid & 31, warp = tid >> 5;
    const int wm = warp >> 1, wn = warp & 1;
    const int mBase = blockIdx.y * 128;
    const int nBase = blockIdx.x * 128;
    float* Cp;
    int ld, cBase;
    if (nBase < split) { Cp = C1; ld = ld1; cBase = nBase; }
    else               { Cp = C2; ld = ld2; cBase = nBase - split; }

    const uint32_t sbase = smem_u32(sm);

    float acc[4][8][4];
#pragma unroll
    for (int i = 0; i < 4; i++)
#pragma unroll
        for (int j = 0; j < 8; j++)
#pragma unroll
            for (int r = 0; r < 4; r++) acc[i][j][r] = 0.f;

    // ---- global load / smem store indexing ----
    const int rowb = tid >> 3;           // 0..15, +16*l
    const int c4   = (tid & 7) * 4;
    const int unit = tid & 7;
    const int rl3  = rowb & 7;
    int dstS[8];
#pragma unroll
    for (int l = 0; l < 8; l++) {
        int row = rowb + 16 * l;
        dstS[l] = row * 32 + ((unit ^ rl3) << 2);
    }

    // ---- ldmatrix lane constants ----
    const int g  = lane >> 3, iL = lane & 7;
    const int rA  = wm * 64 + iL + (g & 1) * 8;
    const int kA  = g >> 1;
    const int rB  = wn * 64 + iL + (g >> 1) * 8;
    const int kB  = g & 1;
    const int rA7 = rA & 7, rB7 = rB & 7;

    float4 aR[8], bR[8];
#pragma unroll
    for (int l = 0; l < 8; l++) {
        int gr = mBase + rowb + 16 * l;
        aR[l] = (gr < M) ? *reinterpret_cast<const float4*>(A + (size_t)gr * K + c4)
                         : make_float4(0.f, 0.f, 0.f, 0.f);
        bR[l] = *reinterpret_cast<const float4*>(Bt + (size_t)(nBase + rowb + 16 * l) * K + c4);
    }
    {
        float* As = sm;
        float* Bs = sm + 4096;
#pragma unroll
        for (int l = 0; l < 8; l++) {
            float4 av = make_float4(to_tf32(aR[l].x), to_tf32(aR[l].y),
                                    to_tf32(aR[l].z), to_tf32(aR[l].w));
            *reinterpret_cast<float4*>(As + dstS[l]) = av;
            *reinterpret_cast<float4*>(Bs + dstS[l]) = bR[l];
        }
    }
    __syncthreads();

    int buf = 0;
    for (int k0 = 32; k0 <= K; k0 += 32) {
        const bool more = (k0 < K);
        if (more) {
#pragma unroll
            for (int l = 0; l < 8; l++) {
                int gr = mBase + rowb + 16 * l;
                aR[l] = (gr < M) ? *reinterpret_cast<const float4*>(A + (size_t)gr * K + k0 + c4)
                                 : make_float4(0.f, 0.f, 0.f, 0.f);
                bR[l] = *reinterpret_cast<const float4*>(Bt + (size_t)(nBase + rowb + 16 * l) * K + k0 + c4);
            }
        }
        // ---- compute current stage ----
        {
            const uint32_t aB = sbase + buf * 32768u;
            const uint32_t bB = aB + 16384u;
#pragma unroll
            for (int kt = 0; kt < 4; kt++) {
                uint32_t a[4][4];
#pragma unroll
                for (int mt = 0; mt < 4; mt++) {
                    uint32_t addr = aB + (uint32_t)(rA + mt * 16) * 128u +
                                    (uint32_t)(((kt * 2 + kA) ^ rA7) << 4);
                    ldsm_x4(a[mt][0], a[mt][1], a[mt][2], a[mt][3], addr);
                }
#pragma unroll
                for (int np = 0; np < 4; np++) {
                    uint32_t b0, b1, b2, b3;
                    uint32_t addr = bB + (uint32_t)(rB + np * 16) * 128u +
                                    (uint32_t)(((kt * 2 + kB) ^ rB7) << 4);
                    ldsm_x4(b0, b1, b2, b3, addr);
#pragma unroll
                    for (int i = 0; i < 4; i++) {
                        mma_tf32(acc[i][2 * np],     a[i][0], a[i][1], a[i][2], a[i][3], b0, b1);
                        mma_tf32(acc[i][2 * np + 1], a[i][0], a[i][1], a[i][2], a[i][3], b2, b3);
                    }
                }
            }
        }
        if (more) {
            float* As = sm + (buf ^ 1) * 8192;
            float* Bs = As + 4096;
#pragma unroll
            for (int l = 0; l < 8; l++) {
                float4 av = make_float4(to_tf32(aR[l].x), to_tf32(aR[l].y),
                                        to_tf32(aR[l].z), to_tf32(aR[l].w));
                *reinterpret_cast<float4*>(As + dstS[l]) = av;
                *reinterpret_cast<float4*>(Bs + dstS[l]) = bR[l];
            }
            __syncthreads();
            buf ^= 1;
        }
    }

    // epilogue: direct float2 stores (C buffers padded to NPAD rows)
#pragma unroll
    for (int i = 0; i < 4; i++) {
        int r0 = mBase + wm * 64 + i * 16 + (lane >> 2);
#pragma unroll
        for (int j = 0; j < 8; j++) {
            int cc = cBase + wn * 64 + j * 8 + (lane & 3) * 2;
            *reinterpret_cast<float2*>(Cp + (size_t)r0 * ld + cc) =
                make_float2(acc[i][j][0], acc[i][j][1]);
            *reinterpret_cast<float2*>(Cp + (size_t)(r0 + 8) * ld + cc) =
                make_float2(acc[i][j][2], acc[i][j][3]);
        }
    }
}

// ---------------- weight transpose (+tf32 round) ----------------------------
__global__ void transpose_cvt(const float* __restrict__ W, float* __restrict__ Wt,
                              int K, int N) {
    __shared__ float t[32][33];
    int kb = blockIdx.y * 32, nb = blockIdx.x * 32;
    for (int i = threadIdx.y; i < 32; i += 8)
        t[i][threadIdx.x] = W[(size_t)(kb + i) * N + nb + threadIdx.x];
    __syncthreads();
    for (int i = threadIdx.y; i < 32; i += 8)
        Wt[(size_t)(nb + i) * K + kb + threadIdx.x] = to_tf32(t[threadIdx.x][i]);
}

// ---------------- CSR build --------------------------------------------------
__global__ void zero_int_kernel(int* __restrict__ p, int n) {
    int i = blockIdx.x * blockDim.x + threadIdx.x;
    if (i < n) p[i] = 0;
}
__global__ void count_deg_kernel(const int* __restrict__ dst, int* __restrict__ deg, int E) {
    int e = blockIdx.x * blockDim.x + threadIdx.x;
    if (e < E) atomicAdd(&deg[dst[e]], 1);
}
__global__ __launch_bounds__(1024)
void scan_kernel(const int* __restrict__ deg, int* __restrict__ rowptr, int n) {
    __shared__ int sums[1024];
    const int chunk = (n + 1023) / 1024;
    const int start = threadIdx.x * chunk;
    int s = 0;
    for (int i = 0; i < chunk; i++) {
        int idx = start + i;
        s += (idx < n) ? deg[idx] : 0;
    }
    sums[threadIdx.x] = s;
    __syncthreads();
    for (int off = 1; off < 1024; off <<= 1) {
        int v = 0;
        if (threadIdx.x >= off) v = sums[threadIdx.x - off];
        __syncthreads();
        if (threadIdx.x >= off) sums[threadIdx.x] += v;
        __syncthreads();
    }
    int base = (threadIdx.x == 0) ? 0 : sums[threadIdx.x - 1];
    for (int i = 0; i < chunk; i++) {
        int idx = start + i;
        if (idx < n) { rowptr[idx] = base; base += deg[idx]; }
    }
    if (threadIdx.x == 1023) rowptr[n] = sums[1023];
}
__global__ void copy_cursor_kernel(const int* __restrict__ rowptr, int* __restrict__ cursor, int n) {
    int i = blockIdx.x * blockDim.x + threadIdx.x;
    if (i < n) cursor[i] = rowptr[i];
}
__global__ void scatter_kernel(const int* __restrict__ dst, int* __restrict__ cursor,
                               int* __restrict__ eids, int E) {
    int e = blockIdx.x * blockDim.x + threadIdx.x;
    if (e < E) {
        int p = atomicAdd(&cursor[dst[e]], 1);
        eids[p] = e;
    }
}

// ---------------- edge / softmax / aggregation -------------------------------
// attn + init of m/den fused (attn always precedes edge_max)
__global__ void attn_kernel(const float* __restrict__ h,
                            const float* __restrict__ att_s,
                            const float* __restrict__ att_d,
                            float* __restrict__ asrc, float* __restrict__ adst,
                            unsigned* __restrict__ m, float* __restrict__ den,
                            int n, int C) {
    int warp = (blockIdx.x * blockDim.x + threadIdx.x) >> 5;
    int lane = threadIdx.x & 31;
    if (warp >= n) return;
    if (lane < 4) { m[warp * 4 + lane] = 0x007FFFFFu; den[warp * 4 + lane] = 0.f; }
    const float* hr = h + (size_t)warp * 4 * C;
#pragma unroll
    for (int hh = 0; hh < 4; hh++) {
        float s1 = 0.f, s2 = 0.f;
        for (int c = lane; c < C; c += 32) {
            float v = hr[hh * C + c];
            s1 += v * att_s[hh * C + c];
            s2 += v * att_d[hh * C + c];
        }
#pragma unroll
        for (int o = 16; o > 0; o >>= 1) {
            s1 += __shfl_down_sync(0xffffffffu, s1, o);
            s2 += __shfl_down_sync(0xffffffffu, s2, o);
        }
        if (lane == 0) { asrc[warp * 4 + hh] = s1; adst[warp * 4 + hh] = s2; }
    }
}

__global__ void edge_max_kernel(const int* __restrict__ src, const int* __restrict__ dst,
                                const float* __restrict__ asrc, const float* __restrict__ adst,
                                float* __restrict__ ebuf, unsigned* __restrict__ m, int E) {
    int e = blockIdx.x * blockDim.x + threadIdx.x;
    if (e >= E) return;
    int s = src[e], d = dst[e];
    float4 a = *reinterpret_cast<const float4*>(asrc + s * 4);
    float4 b = *reinterpret_cast<const float4*>(adst + d * 4);
    float4 v;
    v.x = a.x + b.x; v.x = v.x > 0.f ? v.x : 0.2f * v.x;
    v.y = a.y + b.y; v.y = v.y > 0.f ? v.y : 0.2f * v.y;
    v.z = a.z + b.z; v.z = v.z > 0.f ? v.z : 0.2f * v.z;
    v.w = a.w + b.w; v.w = v.w > 0.f ? v.w : 0.2f * v.w;
    *reinterpret_cast<float4*>(ebuf + e * 4) = v;
    atomicMax(&m[d * 4 + 0], fenc(v.x));
    atomicMax(&m[d * 4 + 1], fenc(v.y));
    atomicMax(&m[d * 4 + 2], fenc(v.z));
    atomicMax(&m[d * 4 + 3], fenc(v.w));
}

__global__ void edge_exp_kernel(const int* __restrict__ dst, const unsigned* __restrict__ m,
                                float* __restrict__ ebuf, float* __restrict__ den, int E) {
    int e = blockIdx.x * blockDim.x + threadIdx.x;
    if (e >= E) return;
    int d = dst[e];
    uint4 mu = *reinterpret_cast<const uint4*>(m + d * 4);
    float4 v = *reinterpret_cast<const float4*>(ebuf + e * 4);
    v.x = expf(v.x - fdec(mu.x));
    v.y = expf(v.y - fdec(mu.y));
    v.z = expf(v.z - fdec(mu.z));
    v.w = expf(v.w - fdec(mu.w));
    *reinterpret_cast<float4*>(ebuf + e * 4) = v;
    atomicAdd(&den[d * 4 + 0], v.x);
    atomicAdd(&den[d * 4 + 1], v.y);
    atomicAdd(&den[d * 4 + 2], v.z);
    atomicAdd(&den[d * 4 + 3], v.w);
}

// CSR pull + finalize fused, layers 0/1 (C=64, HW=256):
// out = elu(agg + b + lin + lb) (tf32-rounded; out only feeds the next GEMM,
// which itself applies cvt.rna -> idempotent, bit-identical).
__global__ __launch_bounds__(256)
void agg_fin_concat(const int* __restrict__ rowptr, const int* __restrict__ eids,
                    const int* __restrict__ src, const float* __restrict__ h,
                    const float* __restrict__ ebuf, const float* __restrict__ den,
                    const float* __restrict__ b, const float* __restrict__ lb,
                    const float* __restrict__ lin, float* __restrict__ out, int n) {
    const int node = blockIdx.x * 8 + (threadIdx.x >> 5);
    if (node >= n) return;
    const int lane = threadIdx.x & 31;
    const int beg = rowptr[node], end = rowptr[node + 1];

    float acc[8];
#pragma unroll
    for (int j = 0; j < 8; j++) acc[j] = 0.f;

    for (int i = beg; i < end; i++) {
        int e = eids[i];
        int s = src[e];
        float4 w4 = *reinterpret_cast<const float4*>(ebuf + (size_t)e * 4);
        float w[4] = {w4.x, w4.y, w4.z, w4.w};
        const float* hs = h + (size_t)s * 256 + lane;
#pragma unroll
        for (int j = 0; j < 8; j++) acc[j] += w[j >> 1] * hs[j * 32];
    }
    float4 d4 = *reinterpret_cast<const float4*>(den + (size_t)node * 4);
    float inv[4] = {1.f / (d4.x + 1e-16f), 1.f / (d4.y + 1e-16f),
                    1.f / (d4.z + 1e-16f), 1.f / (d4.w + 1e-16f)};
#pragma unroll
    for (int j = 0; j < 8; j++) {
        int feat = j * 32 + lane;
        float v = acc[j] * inv[j >> 1] + b[feat] + lin[(size_t)node * 256 + feat] + lb[feat];
        v = v > 0.f ? v : expm1f(v);
        out[(size_t)node * 256 + feat] = v;
    }
}

// CSR pull + finalize fused, layer 2 (C=128, HW=512, head-mean, no activation).
__global__ __launch_bounds__(256)
void agg_fin_mean(const int* __restrict__ rowptr, const int* __restrict__ eids,
                  const int* __restrict__ src, const float* __restrict__ h,
                  const float* __restrict__ ebuf, const float* __restrict__ den,
                  const float* __restrict__ b, const float* __restrict__ lb,
                  const float* __restrict__ lin, float* __restrict__ out, int n) {
    const int node = blockIdx.x * 8 + (threadIdx.x >> 5);
    if (node >= n) return;
    const int lane = threadIdx.x & 31;
    const int beg = rowptr[node], end = rowptr[node + 1];

    float acc[16];
#pragma unroll
    for (int j = 0; j < 16; j++) acc[j] = 0.f;

    for (int i = beg; i < end; i++) {
        int e = eids[i];
        int s = src[e];
        float4 w4 = *reinterpret_cast<const float4*>(ebuf + (size_t)e * 4);
        float w[4] = {w4.x, w4.y, w4.z, w4.w};
        const float* hs = h + (size_t)s * 512 + lane;
#pragma unroll
        for (int j = 0; j < 16; j++) acc[j] += w[j >> 2] * hs[j * 32];
    }
    float4 d4 = *reinterpret_cast<const float4*>(den + (size_t)node * 4);
    float inv[4] = {1.f / (d4.x + 1e-16f), 1.f / (d4.y + 1e-16f),
                    1.f / (d4.z + 1e-16f), 1.f / (d4.w + 1e-16f)};
#pragma unroll
    for (int j = 0; j < 16; j++) acc[j] *= inv[j >> 2];
#pragma unroll
    for (int j2 = 0; j2 < 4; j2++) {
        int feat = j2 * 32 + lane;
        float v = 0.25f * (acc[j2] + acc[j2 + 4] + acc[j2 + 8] + acc[j2 + 12])
                  + b[feat] + lin[(size_t)node * 128 + feat] + lb[feat];
        out[(size_t)node * 128 + feat] = v;
    }
}

// ---------------- host side --------------------------------------------------
static void run_layer_rest(const float* hbuf, const float* as, const float* ad,
                           const float* b, const float* lb, const float* linbuf,
                           int C, float* outbuf, bool last,
                           const int* src, const int* dst,
                           float* asrcb, float* adstb,
                           unsigned* mb, float* denb, float* eb,
                           const int* rowptr, const int* eids, int n, int E) {
    attn_kernel<<<(n + 7) / 8, 256>>>(hbuf, as, ad, asrcb, adstb, mb, denb, n, C);
    edge_max_kernel<<<(E + 255) / 256, 256>>>(src, dst, asrcb, adstb, eb, mb, E);
    edge_exp_kernel<<<(E + 255) / 256, 256>>>(dst, mb, eb, denb, E);
    int nblocks = (n + 7) / 8;
    if (!last)
        agg_fin_concat<<<nblocks, 256>>>(rowptr, eids, src, hbuf, eb, denb, b, lb,
                                         linbuf, outbuf, n);
    else
        agg_fin_mean<<<nblocks, 256>>>(rowptr, eids, src, hbuf, eb, denb, b, lb,
                                       linbuf, outbuf, n);
}

extern "C" void kernel_launch(void* const* d_in, const int* in_sizes, int n_in,
                              void* d_out, int out_size) {
    const float* x  = (const float*)d_in[0];
    const int*   ei = (const int*)d_in[1];
    const int n = in_sizes[0] / 256;   // 50000
    const int E = in_sizes[1] / 2;     // 300000
    const int* src = ei;
    const int* dst = ei + E;

    cudaFuncSetAttribute(gemm_mma, cudaFuncAttributeMaxDynamicSharedMemorySize, GM_SMEM);

    float *hbuf, *linbuf, *b0buf, *b1buf, *asrcb, *adstb, *denb, *eb, *wt;
    unsigned* mb;
    int *deg, *rowptr, *cursor, *eids;
    cudaGetSymbolAddress((void**)&hbuf, g_h);
    cudaGetSymbolAddress((void**)&linbuf, g_lin);
    cudaGetSymbolAddress((void**)&b0buf, g_buf0);
    cudaGetSymbolAddress((void**)&b1buf, g_buf1);
    cudaGetSymbolAddress((void**)&asrcb, g_asrc);
    cudaGetSymbolAddress((void**)&adstb, g_adst);
    cudaGetSymbolAddress((void**)&mb, g_m);
    cudaGetSymbolAddress((void**)&denb, g_den);
    cudaGetSymbolAddress((void**)&eb, g_e);
    cudaGetSymbolAddress((void**)&deg, g_deg);
    cudaGetSymbolAddress((void**)&rowptr, g_rowptr);
    cudaGetSymbolAddress((void**)&cursor, g_cursor);
    cudaGetSymbolAddress((void**)&eids, g_eids);
    cudaGetSymbolAddress((void**)&wt, g_wt);

    // fused weight regions: [gat W ; linear W] stacked in N (rows of Bt)
    float* wt0  = wt;             // 256 + 256 rows (K=256)
    float* lwt0 = wt + 65536;
    float* wt1  = wt + 131072;
    float* lwt1 = wt + 196608;
    float* wt2  = wt + 262144;    // 512 rows
    float* lwt2 = wt + 393216;    // 128 rows

    const int gy = (n + 127) / 128;   // 391
    dim3 tb(32, 8);

    // ordered so the 4th launch (the ncu capture slot) is the big fused GEMM
    transpose_cvt<<<dim3(8, 8), tb>>>((const float*)d_in[2], wt0, 256, 256);
    transpose_cvt<<<dim3(8, 8), tb>>>((const float*)d_in[6], lwt0, 256, 256);
    zero_int_kernel<<<(n + 255) / 256, 256>>>(deg, n);
    gemm_mma<<<dim3(4, gy), 128, GM_SMEM>>>(x, wt0, hbuf, linbuf, n, 256, 256, 256); // 4th
    count_deg_kernel<<<(E + 255) / 256, 256>>>(dst, deg, E);
    scan_kernel<<<1, 1024>>>(deg, rowptr, n);
    copy_cursor_kernel<<<(n + 255) / 256, 256>>>(rowptr, cursor, n);
    scatter_kernel<<<(E + 255) / 256, 256>>>(dst, cursor, eids, E);
    transpose_cvt<<<dim3(8, 8), tb>>>((const float*)d_in[8], wt1, 256, 256);
    transpose_cvt<<<dim3(8, 8), tb>>>((const float*)d_in[12], lwt1, 256, 256);
    transpose_cvt<<<dim3(16, 8), tb>>>((const float*)d_in[14], wt2, 256, 512);
    transpose_cvt<<<dim3(4, 8), tb>>>((const float*)d_in[18], lwt2, 256, 128);

    // layer 0
    run_layer_rest(hbuf, (const float*)d_in[3], (const float*)d_in[4],
                   (const float*)d_in[5], (const float*)d_in[7], linbuf,
                   64, b0buf, false, src, dst, asrcb, adstb,
                   mb, denb, eb, rowptr, eids, n, E);
    // layer 1
    gemm_mma<<<dim3(4, gy), 128, GM_SMEM>>>(b0buf, wt1, hbuf, linbuf, n, 256, 256, 256);
    run_layer_rest(hbuf, (const float*)d_in[9], (const float*)d_in[10],
                   (const float*)d_in[11], (const float*)d_in[13], linbuf,
                   64, b1buf, false, src, dst, asrcb, adstb,
                   mb, denb, eb, rowptr, eids, n, E);
    // layer 2 (fused N = 512 + 128 = 640)
    gemm_mma<<<dim3(5, gy), 128, GM_SMEM>>>(b1buf, wt2, hbuf, linbuf, n, 512, 512, 128);
    run_layer_rest(hbuf, (const float*)d_in[15], (const float*)d_in[16],
                   (const float*)d_in[17], (const float*)d_in[19], linbuf,
                   128, (float*)d_out, true, src, dst, asrcb, adstb,
                   mb, denb, eb, rowptr, eids, n, E);
}

// round 10
// speedup vs baseline: 4.5633x; 1.1310x over previous
#include <cuda_runtime.h>
#include <math.h>
#include <cstdint>

#define NN 50000
#define NE 300000
#define NPAD (NN + 128)

// ---------------- scratch (device globals; no runtime allocation) ----------
__device__ float    g_h   [(size_t)NPAD * 512];
__device__ float    g_lin [(size_t)NPAD * 256];
__device__ float    g_buf0[(size_t)NN * 256];
__device__ float    g_buf1[(size_t)NN * 256];
__device__ float    g_asrc[NN * 4];
__device__ float    g_adst[NN * 4];
__device__ unsigned g_m   [NN * 4];
__device__ float    g_cw  [NE * 4];   // CSR-ordered edge weights (scores -> exp)
__device__ int      g_deg [NN];
__device__ int      g_rowptr[NN + 1];
__device__ int      g_cursor[NN];
__device__ int      g_csrc[NE];       // CSR-ordered source node ids
__device__ int      g_cdst[NE];       // CSR-ordered dest node ids
__device__ int      g_epos[NE];       // edge -> CSR position
__device__ float    g_wt  [425984];   // transposed (tf32-rounded) weights

// ---------------- helpers ---------------------------------------------------
__device__ __forceinline__ float to_tf32(float f) {
    float o;
    asm("cvt.rna.tf32.f32 %0, %1;" : "=f"(o) : "f"(f));
    return o;
}
__device__ __forceinline__ uint32_t smem_u32(const void* p) {
    uint32_t a;
    asm("{ .reg .u64 t; cvta.to.shared.u64 t, %1; cvt.u32.u64 %0, t; }" : "=r"(a) : "l"(p));
    return a;
}
__device__ __forceinline__ void ldsm_x4(uint32_t& r0, uint32_t& r1, uint32_t& r2,
                                        uint32_t& r3, uint32_t addr) {
    asm volatile("ldmatrix.sync.aligned.m8n8.x4.shared.b16 {%0,%1,%2,%3}, [%4];"
                 : "=r"(r0), "=r"(r1), "=r"(r2), "=r"(r3) : "r"(addr));
}
__device__ __forceinline__ void mma_tf32(float* c, uint32_t a0, uint32_t a1,
                                         uint32_t a2, uint32_t a3,
                                         uint32_t b0, uint32_t b1) {
    asm volatile(
        "mma.sync.aligned.m16n8k8.row.col.f32.tf32.tf32.f32 "
        "{%0,%1,%2,%3}, {%4,%5,%6,%7}, {%8,%9}, {%0,%1,%2,%3};"
        : "+f"(c[0]), "+f"(c[1]), "+f"(c[2]), "+f"(c[3])
        : "r"(a0), "r"(a1), "r"(a2), "r"(a3), "r"(b0), "r"(b1));
}
__device__ __forceinline__ unsigned fenc(float f) {
    unsigned u = __float_as_uint(f);
    return (u & 0x80000000u) ? ~u : (u | 0x80000000u);
}
__device__ __forceinline__ float fdec(unsigned u) {
    return (u & 0x80000000u) ? __uint_as_float(u ^ 0x80000000u)
                             : __uint_as_float(~u);
}

// ---------------- tf32 mma.sync GEMM: swizzled smem + ldmatrix (round-7) ----
// C[M, Nt] = A[M, K=256] @ Bt^T, Bt is [Nt, K] row-major tf32-pre-rounded.
// Block 128x128, 128 threads (4 warps 2x2), warp tile 64x64.
#define GM_SMEM 65536

__global__ __launch_bounds__(128, 2)
void gemm_mma(const float* __restrict__ A, const float* __restrict__ Bt,
              float* __restrict__ C1, float* __restrict__ C2,
              int M, int split, int ld1, int ld2) {
    extern __shared__ float sm[];
    const int K = 256;
    const int tid = threadIdx.x, lane = tid & 31, warp = tid >> 5;
    const int wm = warp >> 1, wn = warp & 1;
    const int mBase = blockIdx.y * 128;
    const int nBase = blockIdx.x * 128;
    float* Cp;
    int ld, cBase;
    if (nBase < split) { Cp = C1; ld = ld1; cBase = nBase; }
    else               { Cp = C2; ld = ld2; cBase = nBase - split; }

    const uint32_t sbase = smem_u32(sm);

    float acc[4][8][4];
#pragma unroll
    for (int i = 0; i < 4; i++)
#pragma unroll
        for (int j = 0; j < 8; j++)
#pragma unroll
            for (int r = 0; r < 4; r++) acc[i][j][r] = 0.f;

    const int rowb = tid >> 3;
    const int c4   = (tid & 7) * 4;
    const int unit = tid & 7;
    const int rl3  = rowb & 7;
    int dstS[8];
#pragma unroll
    for (int l = 0; l < 8; l++) {
        int row = rowb + 16 * l;
        dstS[l] = row * 32 + ((unit ^ rl3) << 2);
    }

    const int g  = lane >> 3, iL = lane & 7;
    const int rA  = wm * 64 + iL + (g & 1) * 8;
    const int kA  = g >> 1;
    const int rB  = wn * 64 + iL + (g >> 1) * 8;
    const int kB  = g & 1;
    const int rA7 = rA & 7, rB7 = rB & 7;

    float4 aR[8], bR[8];
#pragma unroll
    for (int l = 0; l < 8; l++) {
        int gr = mBase + rowb + 16 * l;
        aR[l] = (gr < M) ? *reinterpret_cast<const float4*>(A + (size_t)gr * K + c4)
                         : make_float4(0.f, 0.f, 0.f, 0.f);
        bR[l] = *reinterpret_cast<const float4*>(Bt + (size_t)(nBase + rowb + 16 * l) * K + c4);
    }
    {
        float* As = sm;
        float* Bs = sm + 4096;
#pragma unroll
        for (int l = 0; l < 8; l++) {
            float4 av = make_float4(to_tf32(aR[l].x), to_tf32(aR[l].y),
                                    to_tf32(aR[l].z), to_tf32(aR[l].w));
            *reinterpret_cast<float4*>(As + dstS[l]) = av;
            *reinterpret_cast<float4*>(Bs + dstS[l]) = bR[l];
        }
    }
    __syncthreads();

    int buf = 0;
    for (int k0 = 32; k0 <= K; k0 += 32) {
        const bool more = (k0 < K);
        if (more) {
#pragma unroll
            for (int l = 0; l < 8; l++) {
                int gr = mBase + rowb + 16 * l;
                aR[l] = (gr < M) ? *reinterpret_cast<const float4*>(A + (size_t)gr * K + k0 + c4)
                                 : make_float4(0.f, 0.f, 0.f, 0.f);
                bR[l] = *reinterpret_cast<const float4*>(Bt + (size_t)(nBase + rowb + 16 * l) * K + k0 + c4);
            }
        }
        {
            const uint32_t aB = sbase + buf * 32768u;
            const uint32_t bB = aB + 16384u;
#pragma unroll
            for (int kt = 0; kt < 4; kt++) {
                uint32_t a[4][4];
#pragma unroll
                for (int mt = 0; mt < 4; mt++) {
                    uint32_t addr = aB + (uint32_t)(rA + mt * 16) * 128u +
                                    (uint32_t)(((kt * 2 + kA) ^ rA7) << 4);
                    ldsm_x4(a[mt][0], a[mt][1], a[mt][2], a[mt][3], addr);
                }
#pragma unroll
                for (int np = 0; np < 4; np++) {
                    uint32_t b0, b1, b2, b3;
                    uint32_t addr = bB + (uint32_t)(rB + np * 16) * 128u +
                                    (uint32_t)(((kt * 2 + kB) ^ rB7) << 4);
                    ldsm_x4(b0, b1, b2, b3, addr);
#pragma unroll
                    for (int i = 0; i < 4; i++) {
                        mma_tf32(acc[i][2 * np],     a[i][0], a[i][1], a[i][2], a[i][3], b0, b1);
                        mma_tf32(acc[i][2 * np + 1], a[i][0], a[i][1], a[i][2], a[i][3], b2, b3);
                    }
                }
            }
        }
        if (more) {
            float* As = sm + (buf ^ 1) * 8192;
            float* Bs = As + 4096;
#pragma unroll
            for (int l = 0; l < 8; l++) {
                float4 av = make_float4(to_tf32(aR[l].x), to_tf32(aR[l].y),
                                        to_tf32(aR[l].z), to_tf32(aR[l].w));
                *reinterpret_cast<float4*>(As + dstS[l]) = av;
                *reinterpret_cast<float4*>(Bs + dstS[l]) = bR[l];
            }
            __syncthreads();
            buf ^= 1;
        }
    }

#pragma unroll
    for (int i = 0; i < 4; i++) {
        int r0 = mBase + wm * 64 + i * 16 + (lane >> 2);
#pragma unroll
        for (int j = 0; j < 8; j++) {
            int cc = cBase + wn * 64 + j * 8 + (lane & 3) * 2;
            *reinterpret_cast<float2*>(Cp + (size_t)r0 * ld + cc) =
                make_float2(acc[i][j][0], acc[i][j][1]);
            *reinterpret_cast<float2*>(Cp + (size_t)(r0 + 8) * ld + cc) =
                make_float2(acc[i][j][2], acc[i][j][3]);
        }
    }
}

// ---------------- weight transpose (+tf32 round) ----------------------------
__global__ void transpose_cvt(const float* __restrict__ W, float* __restrict__ Wt,
                              int K, int N) {
    __shared__ float t[32][33];
    int kb = blockIdx.y * 32, nb = blockIdx.x * 32;
    for (int i = threadIdx.y; i < 32; i += 8)
        t[i][threadIdx.x] = W[(size_t)(kb + i) * N + nb + threadIdx.x];
    __syncthreads();
    for (int i = threadIdx.y; i < 32; i += 8)
        Wt[(size_t)(nb + i) * K + kb + threadIdx.x] = to_tf32(t[threadIdx.x][i]);
}

// ---------------- CSR build --------------------------------------------------
__global__ void zero_int_kernel(int* __restrict__ p, int n) {
    int i = blockIdx.x * blockDim.x + threadIdx.x;
    if (i < n) p[i] = 0;
}
__global__ void count_deg_kernel(const int* __restrict__ dst, int* __restrict__ deg, int E) {
    int e = blockIdx.x * blockDim.x + threadIdx.x;
    if (e < E) atomicAdd(&deg[dst[e]], 1);
}
__global__ __launch_bounds__(1024)
void scan_kernel(const int* __restrict__ deg, int* __restrict__ rowptr, int n) {
    __shared__ int sums[1024];
    const int chunk = (n + 1023) / 1024;
    const int start = threadIdx.x * chunk;
    int s = 0;
    for (int i = 0; i < chunk; i++) {
        int idx = start + i;
        s += (idx < n) ? deg[idx] : 0;
    }
    sums[threadIdx.x] = s;
    __syncthreads();
    for (int off = 1; off < 1024; off <<= 1) {
        int v = 0;
        if (threadIdx.x >= off) v = sums[threadIdx.x - off];
        __syncthreads();
        if (threadIdx.x >= off) sums[threadIdx.x] += v;
        __syncthreads();
    }
    int base = (threadIdx.x == 0) ? 0 : sums[threadIdx.x - 1];
    for (int i = 0; i < chunk; i++) {
        int idx = start + i;
        if (idx < n) { rowptr[idx] = base; base += deg[idx]; }
    }
    if (threadIdx.x == 1023) rowptr[n] = sums[1023];
}
__global__ void copy_cursor_kernel(const int* __restrict__ rowptr, int* __restrict__ cursor, int n) {
    int i = blockIdx.x * blockDim.x + threadIdx.x;
    if (i < n) cursor[i] = rowptr[i];
}
// scatter: build CSR-ordered src/dst arrays + edge->position map
__global__ void scatter_kernel(const int* __restrict__ src, const int* __restrict__ dst,
                               int* __restrict__ cursor, int* __restrict__ csrc,
                               int* __restrict__ cdst, int* __restrict__ epos, int E) {
    int e = blockIdx.x * blockDim.x + threadIdx.x;
    if (e < E) {
        int d = dst[e];
        int p = atomicAdd(&cursor[d], 1);
        csrc[p] = src[e];
        cdst[p] = d;
        epos[e] = p;
    }
}

// ---------------- edge / softmax / aggregation -------------------------------
// attn + m init fused (attn always precedes edge_max)
__global__ void attn_kernel(const float* __restrict__ h,
                            const float* __restrict__ att_s,
                            const float* __restrict__ att_d,
                            float* __restrict__ asrc, float* __restrict__ adst,
                            unsigned* __restrict__ m, int n, int C) {
    int warp = (blockIdx.x * blockDim.x + threadIdx.x) >> 5;
    int lane = threadIdx.x & 31;
    if (warp >= n) return;
    if (lane < 4) m[warp * 4 + lane] = 0x007FFFFFu;
    const float* hr = h + (size_t)warp * 4 * C;
#pragma unroll
    for (int hh = 0; hh < 4; hh++) {
        float s1 = 0.f, s2 = 0.f;
        for (int c = lane; c < C; c += 32) {
            float v = hr[hh * C + c];
            s1 += v * att_s[hh * C + c];
            s2 += v * att_d[hh * C + c];
        }
#pragma unroll
        for (int o = 16; o > 0; o >>= 1) {
            s1 += __shfl_down_sync(0xffffffffu, s1, o);
            s2 += __shfl_down_sync(0xffffffffu, s2, o);
        }
        if (lane == 0) { asrc[warp * 4 + hh] = s1; adst[warp * 4 + hh] = s2; }
    }
}

// per edge: leaky-relu score -> csr_w[epos[e]], segment max via atomicMax
__global__ void edge_max_kernel(const int* __restrict__ src, const int* __restrict__ dst,
                                const int* __restrict__ epos,
                                const float* __restrict__ asrc, const float* __restrict__ adst,
                                float* __restrict__ cw, unsigned* __restrict__ m, int E) {
    int e = blockIdx.x * blockDim.x + threadIdx.x;
    if (e >= E) return;
    int s = src[e], d = dst[e], p = epos[e];
    float4 a = *reinterpret_cast<const float4*>(asrc + s * 4);
    float4 b = *reinterpret_cast<const float4*>(adst + d * 4);
    float4 v;
    v.x = a.x + b.x; v.x = v.x > 0.f ? v.x : 0.2f * v.x;
    v.y = a.y + b.y; v.y = v.y > 0.f ? v.y : 0.2f * v.y;
    v.z = a.z + b.z; v.z = v.z > 0.f ? v.z : 0.2f * v.z;
    v.w = a.w + b.w; v.w = v.w > 0.f ? v.w : 0.2f * v.w;
    *reinterpret_cast<float4*>(cw + (size_t)p * 4) = v;
    atomicMax(&m[d * 4 + 0], fenc(v.x));
    atomicMax(&m[d * 4 + 1], fenc(v.y));
    atomicMax(&m[d * 4 + 2], fenc(v.z));
    atomicMax(&m[d * 4 + 3], fenc(v.w));
}

// per CSR position: w = exp(w - m[dst]); fully sequential except the m gather
__global__ void edge_exp_kernel(const int* __restrict__ cdst, const unsigned* __restrict__ m,
                                float* __restrict__ cw, int E) {
    int i = blockIdx.x * blockDim.x + threadIdx.x;
    if (i >= E) return;
    int d = cdst[i];
    uint4 mu = *reinterpret_cast<const uint4*>(m + d * 4);
    float4 v = *reinterpret_cast<const float4*>(cw + (size_t)i * 4);
    v.x = expf(v.x - fdec(mu.x));
    v.y = expf(v.y - fdec(mu.y));
    v.z = expf(v.z - fdec(mu.z));
    v.w = expf(v.w - fdec(mu.w));
    *reinterpret_cast<float4*>(cw + (size_t)i * 4) = v;
}

// CSR pull + softmax denom + finalize fused, layers 0/1 (C=64, HW=256):
// one warp per node; sequential csr_src/csr_w streams; float4 h gather.
__global__ __launch_bounds__(256)
void agg_fin_concat(const int* __restrict__ rowptr, const int* __restrict__ csrc,
                    const float* __restrict__ cw, const float* __restrict__ h,
                    const float* __restrict__ b, const float* __restrict__ lb,
                    const float* __restrict__ lin, float* __restrict__ out, int n) {
    const int node = blockIdx.x * 8 + (threadIdx.x >> 5);
    if (node >= n) return;
    const int lane = threadIdx.x & 31;
    const int beg = rowptr[node], end = rowptr[node + 1];
    const bool hiH = (lane & 16) != 0;   // head select within each 128-feat half

    float4 acc0 = make_float4(0.f, 0.f, 0.f, 0.f);
    float4 acc1 = make_float4(0.f, 0.f, 0.f, 0.f);
    float4 ds   = make_float4(0.f, 0.f, 0.f, 0.f);

#pragma unroll 2
    for (int i = beg; i < end; i++) {
        int s = csrc[i];
        float4 w4 = *reinterpret_cast<const float4*>(cw + (size_t)i * 4);
        const float4* hs4 = reinterpret_cast<const float4*>(h + (size_t)s * 256);
        float4 v0 = hs4[lane];
        float4 v1 = hs4[32 + lane];
        float ws0 = hiH ? w4.y : w4.x;
        float ws1 = hiH ? w4.w : w4.z;
        acc0.x += ws0 * v0.x; acc0.y += ws0 * v0.y; acc0.z += ws0 * v0.z; acc0.w += ws0 * v0.w;
        acc1.x += ws1 * v1.x; acc1.y += ws1 * v1.y; acc1.z += ws1 * v1.z; acc1.w += ws1 * v1.w;
        ds.x += w4.x; ds.y += w4.y; ds.z += w4.z; ds.w += w4.w;
    }
    float inv0 = 1.f / ((hiH ? ds.y : ds.x) + 1e-16f);
    float inv1 = 1.f / ((hiH ? ds.w : ds.z) + 1e-16f);

    const float4* b4   = reinterpret_cast<const float4*>(b);
    const float4* lb4  = reinterpret_cast<const float4*>(lb);
    const float4* lin4 = reinterpret_cast<const float4*>(lin + (size_t)node * 256);
    float4* out4 = reinterpret_cast<float4*>(out + (size_t)node * 256);

    float4 bb0 = b4[lane], bb1 = b4[32 + lane];
    float4 lbb0 = lb4[lane], lbb1 = lb4[32 + lane];
    float4 ll0 = lin4[lane], ll1 = lin4[32 + lane];
    float4 r0, r1;
    r0.x = acc0.x * inv0 + bb0.x + ll0.x + lbb0.x;
    r0.y = acc0.y * inv0 + bb0.y + ll0.y + lbb0.y;
    r0.z = acc0.z * inv0 + bb0.z + ll0.z + lbb0.z;
    r0.w = acc0.w * inv0 + bb0.w + ll0.w + lbb0.w;
    r1.x = acc1.x * inv1 + bb1.x + ll1.x + lbb1.x;
    r1.y = acc1.y * inv1 + bb1.y + ll1.y + lbb1.y;
    r1.z = acc1.z * inv1 + bb1.z + ll1.z + lbb1.z;
    r1.w = acc1.w * inv1 + bb1.w + ll1.w + lbb1.w;
    r0.x = r0.x > 0.f ? r0.x : expm1f(r0.x);
    r0.y = r0.y > 0.f ? r0.y : expm1f(r0.y);
    r0.z = r0.z > 0.f ? r0.z : expm1f(r0.z);
    r0.w = r0.w > 0.f ? r0.w : expm1f(r0.w);
    r1.x = r1.x > 0.f ? r1.x : expm1f(r1.x);
    r1.y = r1.y > 0.f ? r1.y : expm1f(r1.y);
    r1.z = r1.z > 0.f ? r1.z : expm1f(r1.z);
    r1.w = r1.w > 0.f ? r1.w : expm1f(r1.w);
    out4[lane] = r0;
    out4[32 + lane] = r1;
}

// CSR pull + denom + finalize fused, layer 2 (C=128, HW=512, head-mean).
__global__ __launch_bounds__(256)
void agg_fin_mean(const int* __restrict__ rowptr, const int* __restrict__ csrc,
                  const float* __restrict__ cw, const float* __restrict__ h,
                  const float* __restrict__ b, const float* __restrict__ lb,
                  const float* __restrict__ lin, float* __restrict__ out, int n) {
    const int node = blockIdx.x * 8 + (threadIdx.x >> 5);
    if (node >= n) return;
    const int lane = threadIdx.x & 31;
    const int beg = rowptr[node], end = rowptr[node + 1];

    float4 acc[4];
#pragma unroll
    for (int q = 0; q < 4; q++) acc[q] = make_float4(0.f, 0.f, 0.f, 0.f);
    float4 ds = make_float4(0.f, 0.f, 0.f, 0.f);

#pragma unroll 2
    for (int i = beg; i < end; i++) {
        int s = csrc[i];
        float4 w4 = *reinterpret_cast<const float4*>(cw + (size_t)i * 4);
        const float4* hs4 = reinterpret_cast<const float4*>(h + (size_t)s * 512);
        float4 v0 = hs4[lane];
        float4 v1 = hs4[32 + lane];
        float4 v2 = hs4[64 + lane];
        float4 v3 = hs4[96 + lane];
        acc[0].x += w4.x * v0.x; acc[0].y += w4.x * v0.y; acc[0].z += w4.x * v0.z; acc[0].w += w4.x * v0.w;
        acc[1].x += w4.y * v1.x; acc[1].y += w4.y * v1.y; acc[1].z += w4.y * v1.z; acc[1].w += w4.y * v1.w;
        acc[2].x += w4.z * v2.x; acc[2].y += w4.z * v2.y; acc[2].z += w4.z * v2.z; acc[2].w += w4.z * v2.w;
        acc[3].x += w4.w * v3.x; acc[3].y += w4.w * v3.y; acc[3].z += w4.w * v3.z; acc[3].w += w4.w * v3.w;
        ds.x += w4.x; ds.y += w4.y; ds.z += w4.z; ds.w += w4.w;
    }
    float i0 = 1.f / (ds.x + 1e-16f);
    float i1 = 1.f / (ds.y + 1e-16f);
    float i2 = 1.f / (ds.z + 1e-16f);
    float i3 = 1.f / (ds.w + 1e-16f);

    const float4* b4   = reinterpret_cast<const float4*>(b);
    const float4* lb4  = reinterpret_cast<const float4*>(lb);
    const float4* lin4 = reinterpret_cast<const float4*>(lin + (size_t)node * 128);
    float4 bb = b4[lane], lbb = lb4[lane], ll = lin4[lane];
    float4 r;
    r.x = 0.25f * (acc[0].x * i0 + acc[1].x * i1 + acc[2].x * i2 + acc[3].x * i3) + bb.x + ll.x + lbb.x;
    r.y = 0.25f * (acc[0].y * i0 + acc[1].y * i1 + acc[2].y * i2 + acc[3].y * i3) + bb.y + ll.y + lbb.y;
    r.z = 0.25f * (acc[0].z * i0 + acc[1].z * i1 + acc[2].z * i2 + acc[3].z * i3) + bb.z + ll.z + lbb.z;
    r.w = 0.25f * (acc[0].w * i0 + acc[1].w * i1 + acc[2].w * i2 + acc[3].w * i3) + bb.w + ll.w + lbb.w;
    reinterpret_cast<float4*>(out + (size_t)node * 128)[lane] = r;
}

// ---------------- host side --------------------------------------------------
static void run_layer_rest(const float* hbuf, const float* as, const float* ad,
                           const float* b, const float* lb, const float* linbuf,
                           int C, float* outbuf, bool last,
                           const int* src, const int* dst, const int* epos,
                           float* asrcb, float* adstb, unsigned* mb, float* cwb,
                           const int* rowptr, const int* csrc, const int* cdst,
                           int n, int E) {
    attn_kernel<<<(n + 7) / 8, 256>>>(hbuf, as, ad, asrcb, adstb, mb, n, C);
    edge_max_kernel<<<(E + 255) / 256, 256>>>(src, dst, epos, asrcb, adstb, cwb, mb, E);
    edge_exp_kernel<<<(E + 255) / 256, 256>>>(cdst, mb, cwb, E);
    int nblocks = (n + 7) / 8;
    if (!last)
        agg_fin_concat<<<nblocks, 256>>>(rowptr, csrc, cwb, hbuf, b, lb, linbuf, outbuf, n);
    else
        agg_fin_mean<<<nblocks, 256>>>(rowptr, csrc, cwb, hbuf, b, lb, linbuf, outbuf, n);
}

extern "C" void kernel_launch(void* const* d_in, const int* in_sizes, int n_in,
                              void* d_out, int out_size) {
    const float* x  = (const float*)d_in[0];
    const int*   ei = (const int*)d_in[1];
    const int n = in_sizes[0] / 256;   // 50000
    const int E = in_sizes[1] / 2;     // 300000
    const int* src = ei;
    const int* dst = ei + E;

    cudaFuncSetAttribute(gemm_mma, cudaFuncAttributeMaxDynamicSharedMemorySize, GM_SMEM);

    float *hbuf, *linbuf, *b0buf, *b1buf, *asrcb, *adstb, *cwb, *wt;
    unsigned* mb;
    int *deg, *rowptr, *cursor, *csrc, *cdst, *epos;
    cudaGetSymbolAddress((void**)&hbuf, g_h);
    cudaGetSymbolAddress((void**)&linbuf, g_lin);
    cudaGetSymbolAddress((void**)&b0buf, g_buf0);
    cudaGetSymbolAddress((void**)&b1buf, g_buf1);
    cudaGetSymbolAddress((void**)&asrcb, g_asrc);
    cudaGetSymbolAddress((void**)&adstb, g_adst);
    cudaGetSymbolAddress((void**)&mb, g_m);
    cudaGetSymbolAddress((void**)&cwb, g_cw);
    cudaGetSymbolAddress((void**)&deg, g_deg);
    cudaGetSymbolAddress((void**)&rowptr, g_rowptr);
    cudaGetSymbolAddress((void**)&cursor, g_cursor);
    cudaGetSymbolAddress((void**)&csrc, g_csrc);
    cudaGetSymbolAddress((void**)&cdst, g_cdst);
    cudaGetSymbolAddress((void**)&epos, g_epos);
    cudaGetSymbolAddress((void**)&wt, g_wt);

    float* wt0  = wt;
    float* lwt0 = wt + 65536;
    float* wt1  = wt + 131072;
    float* lwt1 = wt + 196608;
    float* wt2  = wt + 262144;
    float* lwt2 = wt + 393216;

    const int gy = (n + 127) / 128;   // 391
    dim3 tb(32, 8);

    // ordered so the 4th launch (the ncu capture slot) is the big fused GEMM
    transpose_cvt<<<dim3(8, 8), tb>>>((const float*)d_in[2], wt0, 256, 256);
    transpose_cvt<<<dim3(8, 8), tb>>>((const float*)d_in[6], lwt0, 256, 256);
    zero_int_kernel<<<(n + 255) / 256, 256>>>(deg, n);
    gemm_mma<<<dim3(4, gy), 128, GM_SMEM>>>(x, wt0, hbuf, linbuf, n, 256, 256, 256); // 4th
    count_deg_kernel<<<(E + 255) / 256, 256>>>(dst, deg, E);
    scan_kernel<<<1, 1024>>>(deg, rowptr, n);
    copy_cursor_kernel<<<(n + 255) / 256, 256>>>(rowptr, cursor, n);
    scatter_kernel<<<(E + 255) / 256, 256>>>(src, dst, cursor, csrc, cdst, epos, E);
    transpose_cvt<<<dim3(8, 8), tb>>>((const float*)d_in[8], wt1, 256, 256);
    transpose_cvt<<<dim3(8, 8), tb>>>((const float*)d_in[12], lwt1, 256, 256);
    transpose_cvt<<<dim3(16, 8), tb>>>((const float*)d_in[14], wt2, 256, 512);
    transpose_cvt<<<dim3(4, 8), tb>>>((const float*)d_in[18], lwt2, 256, 128);

    // layer 0
    run_layer_rest(hbuf, (const float*)d_in[3], (const float*)d_in[4],
                   (const float*)d_in[5], (const float*)d_in[7], linbuf,
                   64, b0buf, false, src, dst, epos, asrcb, adstb, mb, cwb,
                   rowptr, csrc, cdst, n, E);
    // layer 1
    gemm_mma<<<dim3(4, gy), 128, GM_SMEM>>>(b0buf, wt1, hbuf, linbuf, n, 256, 256, 256);
    run_layer_rest(hbuf, (const float*)d_in[9], (const float*)d_in[10],
                   (const float*)d_in[11], (const float*)d_in[13], linbuf,
                   64, b1buf, false, src, dst, epos, asrcb, adstb, mb, cwb,
                   rowptr, csrc, cdst, n, E);
    // layer 2 (fused N = 512 + 128 = 640)
    gemm_mma<<<dim3(5, gy), 128, GM_SMEM>>>(b1buf, wt2, hbuf, linbuf, n, 512, 512, 128);
    run_layer_rest(hbuf, (const float*)d_in[15], (const float*)d_in[16],
                   (const float*)d_in[17], (const float*)d_in[19], linbuf,
                   128, (float*)d_out, true, src, dst, epos, asrcb, adstb, mb, cwb,
                   rowptr, csrc, cdst, n, E);
}